// round 1
// baseline (speedup 1.0000x reference)
#include <cuda_runtime.h>
#include <math.h>

#define L  256
#define DM 128
#define NH 4
#define DK 32
#define NP (L*L)   // 65536 pairwise positions

// Scratch (allocation-free rule: __device__ globals)
__device__ float g_zn[NP*DM];     // LayerNorm output
__device__ float g_q[NP*DM];      // [p][h*32+d]
__device__ float g_k[NP*DM];
__device__ float g_v[NP*DM];
__device__ float g_gate[NP*DM];   // sigmoid(zn@Wg+bg)
__device__ float g_att[NP*DM];    // gate * attention-out (flat)
__device__ float g_biasT[NH*NP];  // bias transposed: [h][i*L+j]

// ---------------------------------------------------------------------------
// Kernel 1: LayerNorm over D=128 per position + bias projection zn@Wb (4 cols)
// One block of 128 threads per position.
// ---------------------------------------------------------------------------
__global__ __launch_bounds__(128) void k_ln(const float* __restrict__ z,
                                            const float* __restrict__ ln_w,
                                            const float* __restrict__ ln_b,
                                            const float* __restrict__ Wb)
{
    int p = blockIdx.x;
    int t = threadIdx.x;
    float v = z[p*DM + t];
    float s = v, sq = v*v;
    #pragma unroll
    for (int o=16;o>0;o>>=1){
        s  += __shfl_xor_sync(0xffffffffu, s,  o);
        sq += __shfl_xor_sync(0xffffffffu, sq, o);
    }
    __shared__ float rs[4], rq[4];
    __shared__ float zs[DM];
    int w = t>>5, lane = t&31;
    if (lane==0){ rs[w]=s; rq[w]=sq; }
    __syncthreads();
    s  = rs[0]+rs[1]+rs[2]+rs[3];
    sq = rq[0]+rq[1]+rq[2]+rq[3];
    float mu   = s*(1.0f/DM);
    float var  = fmaxf(sq*(1.0f/DM) - mu*mu, 0.0f);
    float rstd = rsqrtf(var + 1e-5f);
    float zn = (v-mu)*rstd*ln_w[t] + ln_b[t];
    g_zn[p*DM+t] = zn;
    zs[t] = zn;
    __syncthreads();
    // bias: warp w computes head h=w ; store transposed [h][p]
    float acc = 0.f;
    #pragma unroll
    for (int c=lane;c<DM;c+=32) acc += zs[c]*Wb[c*NH + w];
    #pragma unroll
    for (int o=16;o>0;o>>=1) acc += __shfl_xor_sync(0xffffffffu, acc, o);
    if (lane==0) g_biasT[w*NP + p] = acc;
}

// ---------------------------------------------------------------------------
// Kernel 2/4/5: tiled fp32 GEMM  C[65536 x 128] = A[65536 x 128] @ W[128 x 128]
// BM=BN=128, BK=16, 256 threads, 8x8 micro-tile per thread.
// mode: 0->q  1->k  2->v  3->gate(sigmoid(x+bg))  4->out (A=g_att, +bo)
// ---------------------------------------------------------------------------
__global__ __launch_bounds__(256,2) void k_gemm(const float* __restrict__ W,
                                                const float* __restrict__ addv,
                                                float* __restrict__ dout,
                                                int mode)
{
    __shared__ float As[16][128];   // transposed A tile: As[k][m]
    __shared__ float Bs[16][128];   // Bs[k][n]
    int tid = threadIdx.x;
    int tx = tid & 15, ty = tid >> 4;
    int mt = blockIdx.x;
    const float* A = (mode==4) ? g_att : g_zn;
    float* O = (mode==0)?g_q:(mode==1)?g_k:(mode==2)?g_v:(mode==3)?g_gate:dout;
    const float* Ab = A + mt*128*DM;
    float acc[8][8];
    #pragma unroll
    for (int i=0;i<8;i++)
        #pragma unroll
        for (int j=0;j<8;j++) acc[i][j]=0.f;

    for (int kk=0; kk<8; kk++){
        #pragma unroll
        for (int rep=0; rep<2; rep++){
            int idx = tid + rep*256;              // 0..511 float4 slots
            int row = idx>>2, c4 = idx&3;         // A: 128 rows x 4 float4
            float4 a4 = *(const float4*)&Ab[row*DM + kk*16 + c4*4];
            As[c4*4+0][row]=a4.x; As[c4*4+1][row]=a4.y;
            As[c4*4+2][row]=a4.z; As[c4*4+3][row]=a4.w;
            int brow = idx>>5, bc4 = idx&31;      // B: 16 rows x 32 float4
            *(float4*)&Bs[brow][bc4*4] = *(const float4*)&W[(kk*16+brow)*128 + bc4*4];
        }
        __syncthreads();
        #pragma unroll
        for (int k=0;k<16;k++){
            float a[8], b[8];
            *(float4*)&a[0] = *(const float4*)&As[k][ty*8];
            *(float4*)&a[4] = *(const float4*)&As[k][ty*8+4];
            *(float4*)&b[0] = *(const float4*)&Bs[k][tx*8];
            *(float4*)&b[4] = *(const float4*)&Bs[k][tx*8+4];
            #pragma unroll
            for (int i=0;i<8;i++)
                #pragma unroll
                for (int j=0;j<8;j++)
                    acc[i][j] = fmaf(a[i], b[j], acc[i][j]);
        }
        __syncthreads();
    }
    #pragma unroll
    for (int i=0;i<8;i++){
        int m = mt*128 + ty*8 + i;
        float out8[8];
        #pragma unroll
        for (int j=0;j<8;j++){
            float vv = acc[i][j];
            int n = tx*8+j;
            if (mode==3)      vv = 1.f/(1.f + __expf(-(vv + addv[n])));
            else if (mode==4) vv += addv[n];
            out8[j]=vv;
        }
        *(float4*)&O[m*DM + tx*8]   = *(float4*)&out8[0];
        *(float4*)&O[m*DM + tx*8+4] = *(float4*)&out8[4];
    }
}

// ---------------------------------------------------------------------------
// Kernel 3: row-wise attention. Block = (row r, head h), thread = query i.
// Flash-style online softmax over j in 8 tiles of 32; K/V tiles in smem
// (broadcast reads -> conflict-free). Gating fused into epilogue.
// ---------------------------------------------------------------------------
__global__ __launch_bounds__(256) void k_attn(const float* __restrict__ mask)
{
    int r = blockIdx.x, h = blockIdx.y;
    int i = threadIdx.x;
    __shared__ float Ks[32][32];
    __shared__ float Vs[32][32];
    __shared__ float msk[L];
    msk[i] = mask[i];
    float q[32];
    {
        const float4* qp = (const float4*)&g_q[(r*L+i)*DM + h*DK];
        #pragma unroll
        for (int u=0;u<8;u++) *(float4*)&q[u*4] = qp[u];
    }
    float mI = mask[i];
    float mrun = -INFINITY, ssum = 0.f;
    float acc[32];
    #pragma unroll
    for (int d=0;d<32;d++) acc[d]=0.f;
    const float rscale = 0.17677669529663687f;  // 1/sqrt(32)

    for (int jt=0; jt<8; jt++){
        __syncthreads();
        {   // cooperative tile load: 32 rows x 8 float4, one float4/thread
            int row = i>>3, c4 = i&7;
            int g = (r*L + jt*32 + row)*DM + h*DK + c4*4;
            *(float4*)&Ks[row][c4*4] = *(const float4*)&g_k[g];
            *(float4*)&Vs[row][c4*4] = *(const float4*)&g_v[g];
        }
        __syncthreads();
        float lg[32];
        float tmax = -INFINITY;
        #pragma unroll
        for (int j4=0;j4<8;j4++){
            float4 b4 = *(const float4*)&g_biasT[h*NP + i*L + jt*32 + j4*4];
            float bb[4] = {b4.x,b4.y,b4.z,b4.w};
            #pragma unroll
            for (int u=0;u<4;u++){
                int j = j4*4+u;
                float d0=0.f,d1=0.f,d2=0.f,d3=0.f;
                #pragma unroll
                for (int uu=0;uu<8;uu++){
                    float4 k4 = *(const float4*)&Ks[j][uu*4];
                    d0=fmaf(q[uu*4+0],k4.x,d0);
                    d1=fmaf(q[uu*4+1],k4.y,d1);
                    d2=fmaf(q[uu*4+2],k4.z,d2);
                    d3=fmaf(q[uu*4+3],k4.w,d3);
                }
                float l = (d0+d1+d2+d3)*rscale + bb[u];
                if (mI*msk[jt*32+j] <= 0.f) l = -INFINITY;
                lg[j]=l;
                tmax = fmaxf(tmax, l);
            }
        }
        float nm = fmaxf(mrun, tmax);
        float fac = __expf(mrun - nm);      // jt==0: exp(-inf)=0, clean start
        ssum *= fac;
        #pragma unroll
        for (int d=0;d<32;d++) acc[d]*=fac;
        #pragma unroll
        for (int j=0;j<32;j++){
            float p = __expf(lg[j]-nm);
            ssum += p;
            #pragma unroll
            for (int uu=0;uu<8;uu++){
                float4 v4 = *(const float4*)&Vs[j][uu*4];
                acc[uu*4+0]=fmaf(p,v4.x,acc[uu*4+0]);
                acc[uu*4+1]=fmaf(p,v4.y,acc[uu*4+1]);
                acc[uu*4+2]=fmaf(p,v4.z,acc[uu*4+2]);
                acc[uu*4+3]=fmaf(p,v4.w,acc[uu*4+3]);
            }
        }
        mrun = nm;
    }
    float rinv = 1.f/ssum;
    int base = (r*L+i)*DM + h*DK;
    #pragma unroll
    for (int uu=0;uu<8;uu++){
        float4 g4 = *(const float4*)&g_gate[base+uu*4];
        float4 o4;
        o4.x = acc[uu*4+0]*rinv*g4.x;
        o4.y = acc[uu*4+1]*rinv*g4.y;
        o4.z = acc[uu*4+2]*rinv*g4.z;
        o4.w = acc[uu*4+3]*rinv*g4.w;
        *(float4*)&g_att[base+uu*4] = o4;
    }
}

// ---------------------------------------------------------------------------
extern "C" void kernel_launch(void* const* d_in, const int* in_sizes, int n_in,
                              void* d_out, int out_size)
{
    const float* z    = (const float*)d_in[0];
    const float* mask = (const float*)d_in[1];
    const float* ln_w = (const float*)d_in[2];
    const float* ln_b = (const float*)d_in[3];
    const float* Wq   = (const float*)d_in[4];
    const float* Wk   = (const float*)d_in[5];
    const float* Wv   = (const float*)d_in[6];
    const float* Wb   = (const float*)d_in[7];
    const float* Wg   = (const float*)d_in[8];
    const float* bg   = (const float*)d_in[9];
    const float* Wo   = (const float*)d_in[10];
    const float* bo   = (const float*)d_in[11];
    float* out = (float*)d_out;

    k_ln<<<NP, 128>>>(z, ln_w, ln_b, Wb);
    k_gemm<<<NP/128, 256>>>(Wq, bg, nullptr, 0);
    k_gemm<<<NP/128, 256>>>(Wk, bg, nullptr, 1);
    k_gemm<<<NP/128, 256>>>(Wv, bg, nullptr, 2);
    k_gemm<<<NP/128, 256>>>(Wg, bg, nullptr, 3);
    k_attn<<<dim3(L, NH), 256>>>(mask);
    k_gemm<<<NP/128, 256>>>(Wo, bo, out, 4);
}

// round 2
// speedup vs baseline: 1.9596x; 1.9596x over previous
#include <cuda_runtime.h>
#include <math.h>

#define L   256
#define DM  128
#define NH  4
#define DK  32
#define NP  (L*L)

#define SA  132   // smem stride (words) for A-style fragment reads (4g+t4 banks)
#define SB  136   // smem stride (words) for B-style fragment reads (8t4+g banks)
#define SQ  36    // Q/K stride (rows of 32, A/K-read pattern)
#define SV  40    // V stride (B-read pattern)
#define SP  68    // P stride (rows of 64, A-read pattern)

// Scratch (__device__ globals: allocation-free rule)
__device__ float g_zn[NP*DM];
__device__ float g_q[NP*DM];
__device__ float g_k[NP*DM];
__device__ float g_v[NP*DM];
__device__ float g_gate[NP*DM];
__device__ float g_att[NP*DM];
__device__ float g_biasT[NH*NP];   // [h][i*L + j]

// ---------------------------------------------------------------------------
// helpers
// ---------------------------------------------------------------------------
__device__ __forceinline__ unsigned f2tf(float f){
    unsigned u; asm("cvt.rna.tf32.f32 %0, %1;" : "=r"(u) : "f"(f)); return u;
}
__device__ __forceinline__ void mma8(float* c, const unsigned* a, const unsigned* b){
    asm volatile("mma.sync.aligned.m16n8k8.row.col.f32.tf32.tf32.f32 "
        "{%0,%1,%2,%3}, {%4,%5,%6,%7}, {%8,%9}, {%0,%1,%2,%3};\n"
        : "+f"(c[0]), "+f"(c[1]), "+f"(c[2]), "+f"(c[3])
        : "r"(a[0]), "r"(a[1]), "r"(a[2]), "r"(a[3]), "r"(b[0]), "r"(b[1]));
}

// ---------------------------------------------------------------------------
// Kernel 1: LayerNorm (1 warp / position, float4 I/O) + bias projection zn@Wb
// ---------------------------------------------------------------------------
__global__ __launch_bounds__(256) void k_ln2(const float* __restrict__ z,
                                             const float* __restrict__ ln_w,
                                             const float* __restrict__ ln_b,
                                             const float* __restrict__ Wb)
{
    int w = threadIdx.x >> 5, lane = threadIdx.x & 31;
    int p = blockIdx.x*8 + w;
    float4 x = *(const float4*)&z[p*DM + lane*4];
    float s  = x.x + x.y + x.z + x.w;
    float sq = x.x*x.x + x.y*x.y + x.z*x.z + x.w*x.w;
    #pragma unroll
    for (int o=16;o>0;o>>=1){
        s  += __shfl_xor_sync(0xffffffffu, s,  o);
        sq += __shfl_xor_sync(0xffffffffu, sq, o);
    }
    float mu   = s*(1.0f/DM);
    float var  = fmaxf(sq*(1.0f/DM) - mu*mu, 0.0f);
    float rstd = rsqrtf(var + 1e-5f);
    float4 lw = *(const float4*)&ln_w[lane*4];
    float4 lb = *(const float4*)&ln_b[lane*4];
    float4 zn;
    zn.x = (x.x-mu)*rstd*lw.x + lb.x;
    zn.y = (x.y-mu)*rstd*lw.y + lb.y;
    zn.z = (x.z-mu)*rstd*lw.z + lb.z;
    zn.w = (x.w-mu)*rstd*lw.w + lb.w;
    *(float4*)&g_zn[p*DM + lane*4] = zn;
    // bias proj: thread owns channels c=4*lane..+3, Wb rows [c][h]
    float4 w0 = *(const float4*)&Wb[(4*lane+0)*NH];
    float4 w1 = *(const float4*)&Wb[(4*lane+1)*NH];
    float4 w2 = *(const float4*)&Wb[(4*lane+2)*NH];
    float4 w3 = *(const float4*)&Wb[(4*lane+3)*NH];
    float a0 = zn.x*w0.x + zn.y*w1.x + zn.z*w2.x + zn.w*w3.x;
    float a1 = zn.x*w0.y + zn.y*w1.y + zn.z*w2.y + zn.w*w3.y;
    float a2 = zn.x*w0.z + zn.y*w1.z + zn.z*w2.z + zn.w*w3.z;
    float a3 = zn.x*w0.w + zn.y*w1.w + zn.z*w2.w + zn.w*w3.w;
    #pragma unroll
    for (int o=16;o>0;o>>=1){
        a0 += __shfl_xor_sync(0xffffffffu, a0, o);
        a1 += __shfl_xor_sync(0xffffffffu, a1, o);
        a2 += __shfl_xor_sync(0xffffffffu, a2, o);
        a3 += __shfl_xor_sync(0xffffffffu, a3, o);
    }
    if (lane==0){
        g_biasT[0*NP + p] = a0;
        g_biasT[1*NP + p] = a1;
        g_biasT[2*NP + p] = a2;
        g_biasT[3*NP + p] = a3;
    }
}

// ---------------------------------------------------------------------------
// warp-level tf32 GEMM tile: C(32x64) += A(smem)@W(smem), K=128
// warp (wm,wn); thread (g,t4). acc[mt][nt][4].
// ---------------------------------------------------------------------------
__device__ __forceinline__ void gemm_warp(const unsigned* __restrict__ As,
                                          const unsigned* __restrict__ Ws,
                                          float acc[2][8][4],
                                          int wm, int wn, int g, int t4)
{
    #pragma unroll 4
    for (int ks=0; ks<16; ks++){
        int k0 = ks*8;
        unsigned a[2][4];
        #pragma unroll
        for (int mt=0; mt<2; mt++){
            int rb = wm*32 + mt*16 + g;
            a[mt][0] = As[rb*SA     + k0 + t4];
            a[mt][1] = As[(rb+8)*SA + k0 + t4];
            a[mt][2] = As[rb*SA     + k0 + t4 + 4];
            a[mt][3] = As[(rb+8)*SA + k0 + t4 + 4];
        }
        unsigned b[8][2];
        #pragma unroll
        for (int nt=0; nt<8; nt++){
            int col = wn*64 + nt*8 + g;
            b[nt][0] = Ws[(k0+t4  )*SB + col];
            b[nt][1] = Ws[(k0+t4+4)*SB + col];
        }
        #pragma unroll
        for (int mt=0; mt<2; mt++)
            #pragma unroll
            for (int nt=0; nt<8; nt++)
                mma8(acc[mt][nt], a[mt], b[nt]);
    }
}

// ---------------------------------------------------------------------------
// Kernel 2: fused q/k/v/gate projections. A tile loaded (and tf32'd) once.
// ---------------------------------------------------------------------------
__global__ __launch_bounds__(256,1) void k_qkvg(const float* __restrict__ Wq,
                                                const float* __restrict__ Wk,
                                                const float* __restrict__ Wv,
                                                const float* __restrict__ Wg,
                                                const float* __restrict__ bg)
{
    extern __shared__ unsigned sm[];
    unsigned* As = sm;              // 128*SA
    unsigned* Ws = sm + 128*SA;     // 128*SB
    int tid = threadIdx.x;
    int w = tid>>5, lane = tid&31, g = lane>>2, t4 = lane&3;
    int wm = w>>1, wn = w&1;

    const float* Ab = g_zn + (size_t)blockIdx.x*128*DM;
    for (int e = tid; e < 128*32; e += 256){
        int row = e>>5, c4 = e&31;
        float4 v = *(const float4*)&Ab[row*DM + c4*4];
        uint4 u = { f2tf(v.x), f2tf(v.y), f2tf(v.z), f2tf(v.w) };
        *(uint4*)&As[row*SA + c4*4] = u;
    }

    #pragma unroll 1
    for (int mode=0; mode<4; mode++){
        const float* W = (mode==0)?Wq:(mode==1)?Wk:(mode==2)?Wv:Wg;
        float* O = (mode==0)?g_q:(mode==1)?g_k:(mode==2)?g_v:g_gate;
        __syncthreads();
        for (int e = tid; e < 128*32; e += 256){
            int row = e>>5, c4 = e&31;
            float4 v = *(const float4*)&W[row*DM + c4*4];
            uint4 u = { f2tf(v.x), f2tf(v.y), f2tf(v.z), f2tf(v.w) };
            *(uint4*)&Ws[row*SB + c4*4] = u;
        }
        __syncthreads();

        float acc[2][8][4];
        #pragma unroll
        for (int mt=0;mt<2;mt++)
            #pragma unroll
            for (int nt=0;nt<8;nt++)
                #pragma unroll
                for (int u=0;u<4;u++) acc[mt][nt][u]=0.f;

        gemm_warp(As, Ws, acc, wm, wn, g, t4);

        #pragma unroll
        for (int mt=0;mt<2;mt++){
            #pragma unroll
            for (int nt=0;nt<8;nt++){
                int col = wn*64 + nt*8 + 2*t4;
                #pragma unroll
                for (int rp=0;rp<2;rp++){
                    int row = blockIdx.x*128 + wm*32 + mt*16 + g + 8*rp;
                    float v0 = acc[mt][nt][2*rp], v1 = acc[mt][nt][2*rp+1];
                    if (mode==3){
                        v0 = 1.f/(1.f + __expf(-(v0 + bg[col])));
                        v1 = 1.f/(1.f + __expf(-(v1 + bg[col+1])));
                    }
                    float2 o2 = {v0, v1};
                    *(float2*)&O[row*DM + col] = o2;
                }
            }
        }
    }
}

// ---------------------------------------------------------------------------
// Kernel 4: output GEMM  out = g_att @ Wo + bo
// ---------------------------------------------------------------------------
__global__ __launch_bounds__(256,1) void k_out(const float* __restrict__ Wo,
                                               const float* __restrict__ bo,
                                               float* __restrict__ dout)
{
    extern __shared__ unsigned sm[];
    unsigned* As = sm;
    unsigned* Ws = sm + 128*SA;
    int tid = threadIdx.x;
    int w = tid>>5, lane = tid&31, g = lane>>2, t4 = lane&3;
    int wm = w>>1, wn = w&1;

    const float* Ab = g_att + (size_t)blockIdx.x*128*DM;
    for (int e = tid; e < 128*32; e += 256){
        int row = e>>5, c4 = e&31;
        float4 v = *(const float4*)&Ab[row*DM + c4*4];
        uint4 u = { f2tf(v.x), f2tf(v.y), f2tf(v.z), f2tf(v.w) };
        *(uint4*)&As[row*SA + c4*4] = u;
        float4 wv = *(const float4*)&Wo[row*DM + c4*4];
        uint4 wu = { f2tf(wv.x), f2tf(wv.y), f2tf(wv.z), f2tf(wv.w) };
        *(uint4*)&Ws[row*SB + c4*4] = wu;
    }
    __syncthreads();

    float acc[2][8][4];
    #pragma unroll
    for (int mt=0;mt<2;mt++)
        #pragma unroll
        for (int nt=0;nt<8;nt++)
            #pragma unroll
            for (int u=0;u<4;u++) acc[mt][nt][u]=0.f;

    gemm_warp(As, Ws, acc, wm, wn, g, t4);

    #pragma unroll
    for (int mt=0;mt<2;mt++)
        #pragma unroll
        for (int nt=0;nt<8;nt++){
            int col = wn*64 + nt*8 + 2*t4;
            #pragma unroll
            for (int rp=0;rp<2;rp++){
                int row = blockIdx.x*128 + wm*32 + mt*16 + g + 8*rp;
                float2 o2 = { acc[mt][nt][2*rp] + bo[col],
                              acc[mt][nt][2*rp+1] + bo[col+1] };
                *(float2*)&dout[row*DM + col] = o2;
            }
        }
}

// ---------------------------------------------------------------------------
// Kernel 3: tensor-core flash attention per (row r, head h).
// S = QK^T/scale + bias(i,j) (mask), online softmax over j, O = P@V, *gate.
// ---------------------------------------------------------------------------
__global__ __launch_bounds__(256,1) void k_attn2(const float* __restrict__ mask)
{
    extern __shared__ unsigned sm[];
    unsigned* Qs = sm;                      // 256*SQ
    unsigned* Ks = Qs + 256*SQ;             // 256*SQ
    unsigned* Vs = Ks + 256*SQ;             // 256*SV
    unsigned* Ps = Vs + 256*SV;             // 256*SP
    float*   msk = (float*)(Ps + 256*SP);   // 256

    int r = blockIdx.x, h = blockIdx.y;
    int tid = threadIdx.x;
    int w = tid>>5, lane = tid&31, g = lane>>2, t4 = lane&3;
    const float rscale = 0.17677669529663687f; // 1/sqrt(32)

    for (int e = tid; e < 256*8; e += 256){
        int row = e>>3, c4 = e&7;
        int gi = (r*L + row)*DM + h*DK + c4*4;
        float4 q4 = *(const float4*)&g_q[gi];
        float4 k4 = *(const float4*)&g_k[gi];
        float4 v4 = *(const float4*)&g_v[gi];
        uint4 qu = { f2tf(q4.x), f2tf(q4.y), f2tf(q4.z), f2tf(q4.w) };
        uint4 ku = { f2tf(k4.x), f2tf(k4.y), f2tf(k4.z), f2tf(k4.w) };
        uint4 vu = { f2tf(v4.x), f2tf(v4.y), f2tf(v4.z), f2tf(v4.w) };
        *(uint4*)&Qs[row*SQ + c4*4] = qu;
        *(uint4*)&Ks[row*SQ + c4*4] = ku;
        *(uint4*)&Vs[row*SV + c4*4] = vu;
    }
    msk[tid] = mask[tid];
    __syncthreads();

    int rb = w*32;
    float mrun[2][2] = {{-INFINITY,-INFINITY},{-INFINITY,-INFINITY}};
    float ssum[2][2] = {{0.f,0.f},{0.f,0.f}};
    float oacc[2][4][4];
    #pragma unroll
    for (int mt=0;mt<2;mt++)
        #pragma unroll
        for (int nt=0;nt<4;nt++)
            #pragma unroll
            for (int u=0;u<4;u++) oacc[mt][nt][u]=0.f;

    #pragma unroll 1
    for (int jt=0; jt<4; jt++){
        int jb = jt*64;
        // ---- S = Q K^T for 32 rows x 64 j ----
        float sacc[2][8][4];
        #pragma unroll
        for (int mt=0;mt<2;mt++)
            #pragma unroll
            for (int nt=0;nt<8;nt++)
                #pragma unroll
                for (int u=0;u<4;u++) sacc[mt][nt][u]=0.f;
        #pragma unroll
        for (int ks=0; ks<4; ks++){
            int k0 = ks*8;
            unsigned a[2][4];
            #pragma unroll
            for (int mt=0;mt<2;mt++){
                int rr = rb + mt*16 + g;
                a[mt][0] = Qs[rr*SQ     + k0 + t4];
                a[mt][1] = Qs[(rr+8)*SQ + k0 + t4];
                a[mt][2] = Qs[rr*SQ     + k0 + t4 + 4];
                a[mt][3] = Qs[(rr+8)*SQ + k0 + t4 + 4];
            }
            unsigned b[8][2];
            #pragma unroll
            for (int nt=0;nt<8;nt++){
                int jr = jb + nt*8 + g;
                b[nt][0] = Ks[jr*SQ + k0 + t4];
                b[nt][1] = Ks[jr*SQ + k0 + t4 + 4];
            }
            #pragma unroll
            for (int mt=0;mt<2;mt++)
                #pragma unroll
                for (int nt=0;nt<8;nt++)
                    mma8(sacc[mt][nt], a[mt], b[nt]);
        }
        // ---- scale + bias + mask, tile max ----
        float tmax[2][2] = {{-1e30f,-1e30f},{-1e30f,-1e30f}};
        #pragma unroll
        for (int mt=0;mt<2;mt++){
            #pragma unroll
            for (int rp=0;rp<2;rp++){
                int i = rb + mt*16 + g + 8*rp;
                float mi = msk[i];
                #pragma unroll
                for (int nt=0;nt<8;nt++){
                    int j0 = jb + nt*8 + 2*t4;
                    float2 bi = *(const float2*)&g_biasT[h*NP + i*L + j0];
                    float p0 = (mi*msk[j0]   > 0.f) ? 0.f : -1e30f;
                    float p1 = (mi*msk[j0+1] > 0.f) ? 0.f : -1e30f;
                    float s0 = sacc[mt][nt][2*rp]  *rscale + bi.x + p0;
                    float s1 = sacc[mt][nt][2*rp+1]*rscale + bi.y + p1;
                    sacc[mt][nt][2*rp]   = s0;
                    sacc[mt][nt][2*rp+1] = s1;
                    tmax[mt][rp] = fmaxf(tmax[mt][rp], fmaxf(s0,s1));
                }
            }
        }
        #pragma unroll
        for (int mt=0;mt<2;mt++)
            #pragma unroll
            for (int rp=0;rp<2;rp++){
                float t = tmax[mt][rp];
                t = fmaxf(t, __shfl_xor_sync(0xffffffffu, t, 1));
                t = fmaxf(t, __shfl_xor_sync(0xffffffffu, t, 2));
                tmax[mt][rp] = t;
            }
        float fac[2][2];
        #pragma unroll
        for (int mt=0;mt<2;mt++)
            #pragma unroll
            for (int rp=0;rp<2;rp++){
                float nm = fmaxf(mrun[mt][rp], tmax[mt][rp]);
                fac[mt][rp] = __expf(mrun[mt][rp] - nm);   // exp(-inf)=0 first tile
                mrun[mt][rp] = nm;
                ssum[mt][rp] *= fac[mt][rp];
            }
        #pragma unroll
        for (int mt=0;mt<2;mt++)
            #pragma unroll
            for (int nt=0;nt<4;nt++){
                oacc[mt][nt][0]*=fac[mt][0]; oacc[mt][nt][1]*=fac[mt][0];
                oacc[mt][nt][2]*=fac[mt][1]; oacc[mt][nt][3]*=fac[mt][1];
            }
        // ---- p = exp(s-m), row sums, stage P to smem (tf32) ----
        float psum[2][2] = {{0.f,0.f},{0.f,0.f}};
        #pragma unroll
        for (int mt=0;mt<2;mt++){
            #pragma unroll
            for (int rp=0;rp<2;rp++){
                int i = rb + mt*16 + g + 8*rp;
                float m = mrun[mt][rp];
                #pragma unroll
                for (int nt=0;nt<8;nt++){
                    float p0 = __expf(sacc[mt][nt][2*rp]   - m);
                    float p1 = __expf(sacc[mt][nt][2*rp+1] - m);
                    psum[mt][rp] += p0 + p1;
                    int jl = nt*8 + 2*t4;
                    uint2 pu = { f2tf(p0), f2tf(p1) };
                    *(uint2*)&Ps[i*SP + jl] = pu;
                }
            }
        }
        #pragma unroll
        for (int mt=0;mt<2;mt++)
            #pragma unroll
            for (int rp=0;rp<2;rp++){
                float s = psum[mt][rp];
                s += __shfl_xor_sync(0xffffffffu, s, 1);
                s += __shfl_xor_sync(0xffffffffu, s, 2);
                ssum[mt][rp] += s;
            }
        __syncwarp();
        // ---- O += P @ V ----
        #pragma unroll
        for (int ks=0; ks<8; ks++){
            int k0 = ks*8;
            unsigned a[2][4];
            #pragma unroll
            for (int mt=0;mt<2;mt++){
                int rr = rb + mt*16 + g;
                a[mt][0] = Ps[rr*SP     + k0 + t4];
                a[mt][1] = Ps[(rr+8)*SP + k0 + t4];
                a[mt][2] = Ps[rr*SP     + k0 + t4 + 4];
                a[mt][3] = Ps[(rr+8)*SP + k0 + t4 + 4];
            }
            unsigned b[4][2];
            #pragma unroll
            for (int nt=0;nt<4;nt++){
                b[nt][0] = Vs[(jb + k0 + t4    )*SV + nt*8 + g];
                b[nt][1] = Vs[(jb + k0 + t4 + 4)*SV + nt*8 + g];
            }
            #pragma unroll
            for (int mt=0;mt<2;mt++)
                #pragma unroll
                for (int nt=0;nt<4;nt++)
                    mma8(oacc[mt][nt], a[mt], b[nt]);
        }
        __syncwarp();
    }
    // ---- epilogue: normalize, gate, store ----
    float rinv[2][2];
    #pragma unroll
    for (int mt=0;mt<2;mt++)
        #pragma unroll
        for (int rp=0;rp<2;rp++) rinv[mt][rp] = 1.f/ssum[mt][rp];
    #pragma unroll
    for (int mt=0;mt<2;mt++)
        #pragma unroll
        for (int nt=0;nt<4;nt++)
            #pragma unroll
            for (int rp=0;rp<2;rp++){
                int i = rb + mt*16 + g + 8*rp;
                int d = nt*8 + 2*t4;
                int gi = (r*L + i)*DM + h*DK + d;
                float2 gt = *(const float2*)&g_gate[gi];
                float2 o2 = { oacc[mt][nt][2*rp]  *rinv[mt][rp]*gt.x,
                              oacc[mt][nt][2*rp+1]*rinv[mt][rp]*gt.y };
                *(float2*)&g_att[gi] = o2;
            }
}

// ---------------------------------------------------------------------------
extern "C" void kernel_launch(void* const* d_in, const int* in_sizes, int n_in,
                              void* d_out, int out_size)
{
    const float* z    = (const float*)d_in[0];
    const float* mask = (const float*)d_in[1];
    const float* ln_w = (const float*)d_in[2];
    const float* ln_b = (const float*)d_in[3];
    const float* Wq   = (const float*)d_in[4];
    const float* Wk   = (const float*)d_in[5];
    const float* Wv   = (const float*)d_in[6];
    const float* Wb   = (const float*)d_in[7];
    const float* Wg   = (const float*)d_in[8];
    const float* bg   = (const float*)d_in[9];
    const float* Wo   = (const float*)d_in[10];
    const float* bo   = (const float*)d_in[11];
    float* out = (float*)d_out;

    const int GEMM_SMEM = (128*SA + 128*SB)*4;                        // 137216
    const int ATT_SMEM  = (256*SQ + 256*SQ + 256*SV + 256*SP + 256)*4; // 185344
    cudaFuncSetAttribute(k_qkvg,  cudaFuncAttributeMaxDynamicSharedMemorySize, GEMM_SMEM);
    cudaFuncSetAttribute(k_out,   cudaFuncAttributeMaxDynamicSharedMemorySize, GEMM_SMEM);
    cudaFuncSetAttribute(k_attn2, cudaFuncAttributeMaxDynamicSharedMemorySize, ATT_SMEM);

    k_ln2 <<<NP/8, 256>>>(z, ln_w, ln_b, Wb);
    k_qkvg<<<NP/128, 256, GEMM_SMEM>>>(Wq, Wk, Wv, Wg, bg);
    k_attn2<<<dim3(L, NH), 256, ATT_SMEM>>>(mask);
    k_out <<<NP/128, 256, GEMM_SMEM>>>(Wo, bo, out);
}

// round 3
// speedup vs baseline: 2.5896x; 1.3215x over previous
#include <cuda_runtime.h>
#include <math.h>

#define L   256
#define DM  128
#define NH  4
#define DK  32
#define NP  (L*L)

#define SA  132   // A-tile stride (words): bank = 4g+t4 pattern, conflict-free
#define SB  136   // B-tile stride: bank = 8t4+g, conflict-free
#define SQ  36    // Q/K stride
#define SV  40    // V stride
#define SP  68    // P stride

// Scratch (__device__ globals: allocation-free rule)
__device__ float g_q[NP*DM];
__device__ float g_k[NP*DM];
__device__ float g_v[NP*DM];
__device__ float g_gate[NP*DM];
__device__ float g_att[NP*DM];
__device__ float g_biasT[NH*NP];   // [h][i*L + j]

__device__ __forceinline__ unsigned f2tf(float f){
    unsigned u; asm("cvt.rna.tf32.f32 %0, %1;" : "=r"(u) : "f"(f)); return u;
}
__device__ __forceinline__ void mma8(float* c, const unsigned* a, const unsigned* b){
    asm volatile("mma.sync.aligned.m16n8k8.row.col.f32.tf32.tf32.f32 "
        "{%0,%1,%2,%3}, {%4,%5,%6,%7}, {%8,%9}, {%0,%1,%2,%3};\n"
        : "+f"(c[0]), "+f"(c[1]), "+f"(c[2]), "+f"(c[3])
        : "r"(a[0]), "r"(a[1]), "r"(a[2]), "r"(a[3]), "r"(b[0]), "r"(b[1]));
}

// ---------------------------------------------------------------------------
// warp-tile GEMM: C(32x32) += A@W, K=128, 16 warps in 4x4 grid
// ---------------------------------------------------------------------------
__device__ __forceinline__ void gemm_warp16(const unsigned* __restrict__ As,
                                            const unsigned* __restrict__ Ws,
                                            float acc[2][4][4],
                                            int wm, int wn, int g, int t4)
{
    #pragma unroll 4
    for (int ks=0; ks<16; ks++){
        int k0 = ks*8;
        unsigned a[2][4];
        #pragma unroll
        for (int mt=0; mt<2; mt++){
            int rb = wm*32 + mt*16 + g;
            a[mt][0] = As[rb*SA     + k0 + t4];
            a[mt][1] = As[(rb+8)*SA + k0 + t4];
            a[mt][2] = As[rb*SA     + k0 + t4 + 4];
            a[mt][3] = As[(rb+8)*SA + k0 + t4 + 4];
        }
        unsigned b[4][2];
        #pragma unroll
        for (int nt=0; nt<4; nt++){
            int col = wn*32 + nt*8 + g;
            b[nt][0] = Ws[(k0+t4  )*SB + col];
            b[nt][1] = Ws[(k0+t4+4)*SB + col];
        }
        #pragma unroll
        for (int mt=0; mt<2; mt++)
            #pragma unroll
            for (int nt=0; nt<4; nt++)
                mma8(acc[mt][nt], a[mt], b[nt]);
    }
}

// ---------------------------------------------------------------------------
// Kernel 1: fused LN + bias-proj + q/k/v/gate projections (512 thr, 16 warps)
// ---------------------------------------------------------------------------
__global__ __launch_bounds__(512,1) void k_qkvg(const float* __restrict__ z,
                                                const float* __restrict__ ln_w,
                                                const float* __restrict__ ln_b,
                                                const float* __restrict__ Wb,
                                                const float* __restrict__ Wq,
                                                const float* __restrict__ Wk,
                                                const float* __restrict__ Wv,
                                                const float* __restrict__ Wg,
                                                const float* __restrict__ bg)
{
    extern __shared__ unsigned sm[];
    unsigned* As = sm;              // 128*SA
    unsigned* Ws = sm + 128*SA;     // 128*SB
    int tid = threadIdx.x;
    int w = tid>>5, lane = tid&31, g = lane>>2, t4 = lane&3;
    int wm = w>>2, wn = w&3;
    int p0 = blockIdx.x*128;

    // ---- LayerNorm + bias projection: warp w owns rows w*8..w*8+7 ----
    {
        float4 lw = *(const float4*)&ln_w[lane*4];
        float4 lb = *(const float4*)&ln_b[lane*4];
        float4 w0 = *(const float4*)&Wb[(4*lane+0)*NH];
        float4 w1 = *(const float4*)&Wb[(4*lane+1)*NH];
        float4 w2 = *(const float4*)&Wb[(4*lane+2)*NH];
        float4 w3 = *(const float4*)&Wb[(4*lane+3)*NH];
        #pragma unroll 2
        for (int rr=0; rr<8; rr++){
            int row = w*8 + rr;
            float4 x = *(const float4*)&z[(size_t)(p0+row)*DM + lane*4];
            float s  = x.x+x.y+x.z+x.w;
            float sq = x.x*x.x + x.y*x.y + x.z*x.z + x.w*x.w;
            #pragma unroll
            for (int o=16;o>0;o>>=1){
                s  += __shfl_xor_sync(0xffffffffu, s,  o);
                sq += __shfl_xor_sync(0xffffffffu, sq, o);
            }
            float mu   = s*(1.0f/DM);
            float var  = fmaxf(sq*(1.0f/DM) - mu*mu, 0.0f);
            float rstd = rsqrtf(var + 1e-5f);
            float4 zn;
            zn.x = (x.x-mu)*rstd*lw.x + lb.x;
            zn.y = (x.y-mu)*rstd*lw.y + lb.y;
            zn.z = (x.z-mu)*rstd*lw.z + lb.z;
            zn.w = (x.w-mu)*rstd*lw.w + lb.w;
            uint4 u = { f2tf(zn.x), f2tf(zn.y), f2tf(zn.z), f2tf(zn.w) };
            *(uint4*)&As[row*SA + lane*4] = u;
            float a0 = zn.x*w0.x + zn.y*w1.x + zn.z*w2.x + zn.w*w3.x;
            float a1 = zn.x*w0.y + zn.y*w1.y + zn.z*w2.y + zn.w*w3.y;
            float a2 = zn.x*w0.z + zn.y*w1.z + zn.z*w2.z + zn.w*w3.z;
            float a3 = zn.x*w0.w + zn.y*w1.w + zn.z*w2.w + zn.w*w3.w;
            #pragma unroll
            for (int o=16;o>0;o>>=1){
                a0 += __shfl_xor_sync(0xffffffffu, a0, o);
                a1 += __shfl_xor_sync(0xffffffffu, a1, o);
                a2 += __shfl_xor_sync(0xffffffffu, a2, o);
                a3 += __shfl_xor_sync(0xffffffffu, a3, o);
            }
            if (lane==0){
                g_biasT[0*NP + p0+row] = a0;
                g_biasT[1*NP + p0+row] = a1;
                g_biasT[2*NP + p0+row] = a2;
                g_biasT[3*NP + p0+row] = a3;
            }
        }
    }

    // ---- 4 projections reuse the A tile ----
    #pragma unroll 1
    for (int mode=0; mode<4; mode++){
        const float* W = (mode==0)?Wq:(mode==1)?Wk:(mode==2)?Wv:Wg;
        float* O = (mode==0)?g_q:(mode==1)?g_k:(mode==2)?g_v:g_gate;
        __syncthreads();
        for (int e = tid; e < 128*32; e += 512){
            int row = e>>5, c4 = e&31;
            float4 v = *(const float4*)&W[row*DM + c4*4];
            uint4 u = { f2tf(v.x), f2tf(v.y), f2tf(v.z), f2tf(v.w) };
            *(uint4*)&Ws[row*SB + c4*4] = u;
        }
        __syncthreads();

        float acc[2][4][4];
        #pragma unroll
        for (int mt=0;mt<2;mt++)
            #pragma unroll
            for (int nt=0;nt<4;nt++)
                #pragma unroll
                for (int u=0;u<4;u++) acc[mt][nt][u]=0.f;

        gemm_warp16(As, Ws, acc, wm, wn, g, t4);

        #pragma unroll
        for (int mt=0;mt<2;mt++)
            #pragma unroll
            for (int nt=0;nt<4;nt++){
                int col = wn*32 + nt*8 + 2*t4;
                #pragma unroll
                for (int rp=0;rp<2;rp++){
                    int row = p0 + wm*32 + mt*16 + g + 8*rp;
                    float v0 = acc[mt][nt][2*rp], v1 = acc[mt][nt][2*rp+1];
                    if (mode==3){
                        v0 = 1.f/(1.f + __expf(-(v0 + bg[col])));
                        v1 = 1.f/(1.f + __expf(-(v1 + bg[col+1])));
                    }
                    float2 o2 = {v0, v1};
                    *(float2*)&O[(size_t)row*DM + col] = o2;
                }
            }
    }
}

// ---------------------------------------------------------------------------
// Kernel 3: output GEMM out = g_att @ Wo + bo (512 thr, 16 warps)
// ---------------------------------------------------------------------------
__global__ __launch_bounds__(512,1) void k_out(const float* __restrict__ Wo,
                                               const float* __restrict__ bo,
                                               float* __restrict__ dout)
{
    extern __shared__ unsigned sm[];
    unsigned* As = sm;
    unsigned* Ws = sm + 128*SA;
    int tid = threadIdx.x;
    int w = tid>>5, lane = tid&31, g = lane>>2, t4 = lane&3;
    int wm = w>>2, wn = w&3;

    const float* Ab = g_att + (size_t)blockIdx.x*128*DM;
    for (int e = tid; e < 128*32; e += 512){
        int row = e>>5, c4 = e&31;
        float4 v = *(const float4*)&Ab[row*DM + c4*4];
        uint4 u = { f2tf(v.x), f2tf(v.y), f2tf(v.z), f2tf(v.w) };
        *(uint4*)&As[row*SA + c4*4] = u;
        float4 wv = *(const float4*)&Wo[row*DM + c4*4];
        uint4 wu = { f2tf(wv.x), f2tf(wv.y), f2tf(wv.z), f2tf(wv.w) };
        *(uint4*)&Ws[row*SB + c4*4] = wu;
    }
    __syncthreads();

    float acc[2][4][4];
    #pragma unroll
    for (int mt=0;mt<2;mt++)
        #pragma unroll
        for (int nt=0;nt<4;nt++)
            #pragma unroll
            for (int u=0;u<4;u++) acc[mt][nt][u]=0.f;

    gemm_warp16(As, Ws, acc, wm, wn, g, t4);

    #pragma unroll
    for (int mt=0;mt<2;mt++)
        #pragma unroll
        for (int nt=0;nt<4;nt++){
            int col = wn*32 + nt*8 + 2*t4;
            #pragma unroll
            for (int rp=0;rp<2;rp++){
                int row = blockIdx.x*128 + wm*32 + mt*16 + g + 8*rp;
                float2 o2 = { acc[mt][nt][2*rp] + bo[col],
                              acc[mt][nt][2*rp+1] + bo[col+1] };
                *(float2*)&dout[(size_t)row*DM + col] = o2;
            }
        }
}

// ---------------------------------------------------------------------------
// Kernel 2: tensor-core attention per (row r, head h). 512 thr, 16 warps,
// warp owns 16 query rows. No-max softmax (logits bounded), mask kept.
// ---------------------------------------------------------------------------
__global__ __launch_bounds__(512,1) void k_attn(const float* __restrict__ mask)
{
    extern __shared__ unsigned sm[];
    unsigned* Qs = sm;                      // 256*SQ
    unsigned* Ks = Qs + 256*SQ;
    unsigned* Vs = Ks + 256*SQ;             // 256*SV
    unsigned* Ps = Vs + 256*SV;             // 256*SP
    float*   msk = (float*)(Ps + 256*SP);   // 256

    int r = blockIdx.x, h = blockIdx.y;
    int tid = threadIdx.x;
    int w = tid>>5, lane = tid&31, g = lane>>2, t4 = lane&3;
    const float rscale = 0.17677669529663687f; // 1/sqrt(32)

    for (int e = tid; e < 256*8; e += 512){
        int row = e>>3, c4 = e&7;
        size_t gi = (size_t)(r*L + row)*DM + h*DK + c4*4;
        float4 q4 = *(const float4*)&g_q[gi];
        float4 k4 = *(const float4*)&g_k[gi];
        float4 v4 = *(const float4*)&g_v[gi];
        uint4 qu = { f2tf(q4.x), f2tf(q4.y), f2tf(q4.z), f2tf(q4.w) };
        uint4 ku = { f2tf(k4.x), f2tf(k4.y), f2tf(k4.z), f2tf(k4.w) };
        uint4 vu = { f2tf(v4.x), f2tf(v4.y), f2tf(v4.z), f2tf(v4.w) };
        *(uint4*)&Qs[row*SQ + c4*4] = qu;
        *(uint4*)&Ks[row*SQ + c4*4] = ku;
        *(uint4*)&Vs[row*SV + c4*4] = vu;
    }
    if (tid < 256) msk[tid] = mask[tid];
    __syncthreads();

    int rb = w*16;
    // Q fragments in registers (warp-private rows)
    unsigned qa[4][4];
    #pragma unroll
    for (int ks=0; ks<4; ks++){
        int k0 = ks*8;
        qa[ks][0] = Qs[(rb+g  )*SQ + k0 + t4];
        qa[ks][1] = Qs[(rb+g+8)*SQ + k0 + t4];
        qa[ks][2] = Qs[(rb+g  )*SQ + k0 + t4 + 4];
        qa[ks][3] = Qs[(rb+g+8)*SQ + k0 + t4 + 4];
    }
    float mi0 = msk[rb+g], mi1 = msk[rb+g+8];
    float ssum[2] = {0.f, 0.f};
    float oacc[4][4];
    #pragma unroll
    for (int nt=0;nt<4;nt++)
        #pragma unroll
        for (int u=0;u<4;u++) oacc[nt][u]=0.f;

    #pragma unroll 1
    for (int jt=0; jt<4; jt++){
        int jb = jt*64;
        float sacc[8][4];
        #pragma unroll
        for (int nt=0;nt<8;nt++)
            #pragma unroll
            for (int u=0;u<4;u++) sacc[nt][u]=0.f;
        #pragma unroll
        for (int ks=0; ks<4; ks++){
            int k0 = ks*8;
            unsigned b[8][2];
            #pragma unroll
            for (int nt=0;nt<8;nt++){
                int jr = jb + nt*8 + g;
                b[nt][0] = Ks[jr*SQ + k0 + t4];
                b[nt][1] = Ks[jr*SQ + k0 + t4 + 4];
            }
            #pragma unroll
            for (int nt=0;nt<8;nt++)
                mma8(sacc[nt], qa[ks], b[nt]);
        }
        // bias + mask + exp (no max subtraction: logits bounded), stage P
        float psum[2] = {0.f, 0.f};
        #pragma unroll
        for (int nt=0;nt<8;nt++){
            int j0 = jb + nt*8 + 2*t4;
            float mj0 = msk[j0], mj1 = msk[j0+1];
            #pragma unroll
            for (int rp=0;rp<2;rp++){
                int i = rb + g + 8*rp;
                float mi = rp ? mi1 : mi0;
                float2 bi = *(const float2*)&g_biasT[h*NP + i*L + j0];
                float s0 = sacc[nt][2*rp]  *rscale + bi.x;
                float s1 = sacc[nt][2*rp+1]*rscale + bi.y;
                float p0 = (mi*mj0 > 0.f) ? __expf(s0) : 0.f;
                float p1 = (mi*mj1 > 0.f) ? __expf(s1) : 0.f;
                psum[rp] += p0 + p1;
                uint2 pu = { f2tf(p0), f2tf(p1) };
                *(uint2*)&Ps[i*SP + nt*8 + 2*t4] = pu;
            }
        }
        #pragma unroll
        for (int rp=0;rp<2;rp++){
            float s = psum[rp];
            s += __shfl_xor_sync(0xffffffffu, s, 1);
            s += __shfl_xor_sync(0xffffffffu, s, 2);
            ssum[rp] += s;
        }
        __syncwarp();
        // O += P @ V
        #pragma unroll
        for (int kc=0; kc<8; kc++){
            int k0 = kc*8;
            unsigned a[4];
            a[0] = Ps[(rb+g  )*SP + k0 + t4];
            a[1] = Ps[(rb+g+8)*SP + k0 + t4];
            a[2] = Ps[(rb+g  )*SP + k0 + t4 + 4];
            a[3] = Ps[(rb+g+8)*SP + k0 + t4 + 4];
            unsigned b[4][2];
            #pragma unroll
            for (int nt=0;nt<4;nt++){
                b[nt][0] = Vs[(jb+k0+t4  )*SV + nt*8 + g];
                b[nt][1] = Vs[(jb+k0+t4+4)*SV + nt*8 + g];
            }
            #pragma unroll
            for (int nt=0;nt<4;nt++)
                mma8(oacc[nt], a, b[nt]);
        }
        __syncwarp();
    }
    // epilogue: normalize, gate, store
    float rinv[2] = { 1.f/ssum[0], 1.f/ssum[1] };
    #pragma unroll
    for (int nt=0;nt<4;nt++)
        #pragma unroll
        for (int rp=0;rp<2;rp++){
            int i = rb + g + 8*rp;
            int d = nt*8 + 2*t4;
            size_t gi = (size_t)(r*L + i)*DM + h*DK + d;
            float2 gt = *(const float2*)&g_gate[gi];
            float2 o2 = { oacc[nt][2*rp]  *rinv[rp]*gt.x,
                          oacc[nt][2*rp+1]*rinv[rp]*gt.y };
            *(float2*)&g_att[gi] = o2;
        }
}

// ---------------------------------------------------------------------------
extern "C" void kernel_launch(void* const* d_in, const int* in_sizes, int n_in,
                              void* d_out, int out_size)
{
    const float* z    = (const float*)d_in[0];
    const float* mask = (const float*)d_in[1];
    const float* ln_w = (const float*)d_in[2];
    const float* ln_b = (const float*)d_in[3];
    const float* Wq   = (const float*)d_in[4];
    const float* Wk   = (const float*)d_in[5];
    const float* Wv   = (const float*)d_in[6];
    const float* Wb   = (const float*)d_in[7];
    const float* Wg   = (const float*)d_in[8];
    const float* bg   = (const float*)d_in[9];
    const float* Wo   = (const float*)d_in[10];
    const float* bo   = (const float*)d_in[11];
    float* out = (float*)d_out;

    const int GEMM_SMEM = (128*SA + 128*SB)*4;                          // 137216
    const int ATT_SMEM  = (256*SQ + 256*SQ + 256*SV + 256*SP + 256)*4;  // 185344
    cudaFuncSetAttribute(k_qkvg, cudaFuncAttributeMaxDynamicSharedMemorySize, GEMM_SMEM);
    cudaFuncSetAttribute(k_out,  cudaFuncAttributeMaxDynamicSharedMemorySize, GEMM_SMEM);
    cudaFuncSetAttribute(k_attn, cudaFuncAttributeMaxDynamicSharedMemorySize, ATT_SMEM);

    k_qkvg<<<NP/128, 512, GEMM_SMEM>>>(z, ln_w, ln_b, Wb, Wq, Wk, Wv, Wg, bg);
    k_attn<<<dim3(L, NH), 512, ATT_SMEM>>>(mask);
    k_out <<<NP/128, 512, GEMM_SMEM>>>(Wo, bo, out);
}

// round 4
// speedup vs baseline: 2.5912x; 1.0006x over previous
#include <cuda_runtime.h>
#include <math.h>

#define L   256
#define DM  128
#define NH  4
#define DK  32
#define NP  (L*L)

#define SA  132   // A-tile stride (words): bank = 4g+t4 pattern, conflict-free
#define SB  136   // B-tile stride: bank = 8t4+g, conflict-free
#define SQ  36    // Q/K stride
#define SV  40    // V stride
#define SP  68    // P stride

// Scratch (__device__ globals: allocation-free rule)
__device__ float g_q[NP*DM];
__device__ float g_k[NP*DM];
__device__ float g_v[NP*DM];
__device__ float g_gate[NP*DM];
__device__ float g_att[NP*DM];
__device__ float g_biasT[NH*NP];   // [h][i*L + j]

__device__ __forceinline__ unsigned f2tf(float f){
    unsigned u; asm("cvt.rna.tf32.f32 %0, %1;" : "=r"(u) : "f"(f)); return u;
}
__device__ __forceinline__ void mma8(float* c, const unsigned* a, const unsigned* b){
    asm volatile("mma.sync.aligned.m16n8k8.row.col.f32.tf32.tf32.f32 "
        "{%0,%1,%2,%3}, {%4,%5,%6,%7}, {%8,%9}, {%0,%1,%2,%3};\n"
        : "+f"(c[0]), "+f"(c[1]), "+f"(c[2]), "+f"(c[3])
        : "r"(a[0]), "r"(a[1]), "r"(a[2]), "r"(a[3]), "r"(b[0]), "r"(b[1]));
}

// ---------------------------------------------------------------------------
// warp-tile GEMM: C(32x32) += A@W, K=128, 16 warps in 4x4 grid
// ---------------------------------------------------------------------------
__device__ __forceinline__ void gemm_warp16(const unsigned* __restrict__ As,
                                            const unsigned* __restrict__ Ws,
                                            float acc[2][4][4],
                                            int wm, int wn, int g, int t4)
{
    #pragma unroll 4
    for (int ks=0; ks<16; ks++){
        int k0 = ks*8;
        unsigned a[2][4];
        #pragma unroll
        for (int mt=0; mt<2; mt++){
            int rb = wm*32 + mt*16 + g;
            a[mt][0] = As[rb*SA     + k0 + t4];
            a[mt][1] = As[(rb+8)*SA + k0 + t4];
            a[mt][2] = As[rb*SA     + k0 + t4 + 4];
            a[mt][3] = As[(rb+8)*SA + k0 + t4 + 4];
        }
        unsigned b[4][2];
        #pragma unroll
        for (int nt=0; nt<4; nt++){
            int col = wn*32 + nt*8 + g;
            b[nt][0] = Ws[(k0+t4  )*SB + col];
            b[nt][1] = Ws[(k0+t4+4)*SB + col];
        }
        #pragma unroll
        for (int mt=0; mt<2; mt++)
            #pragma unroll
            for (int nt=0; nt<4; nt++)
                mma8(acc[mt][nt], a[mt], b[nt]);
    }
}

// ---------------------------------------------------------------------------
// Kernel 1: fused LN + bias-proj + q/k/v/gate projections (512 thr, 16 warps)
// ---------------------------------------------------------------------------
__global__ __launch_bounds__(512,1) void k_qkvg(const float* __restrict__ z,
                                                const float* __restrict__ ln_w,
                                                const float* __restrict__ ln_b,
                                                const float* __restrict__ Wb,
                                                const float* __restrict__ Wq,
                                                const float* __restrict__ Wk,
                                                const float* __restrict__ Wv,
                                                const float* __restrict__ Wg,
                                                const float* __restrict__ bg)
{
    extern __shared__ unsigned sm[];
    unsigned* As = sm;              // 128*SA
    unsigned* Ws = sm + 128*SA;     // 128*SB
    int tid = threadIdx.x;
    int w = tid>>5, lane = tid&31, g = lane>>2, t4 = lane&3;
    int wm = w>>2, wn = w&3;
    int p0 = blockIdx.x*128;

    // ---- LayerNorm + bias projection: warp w owns rows w*8..w*8+7 ----
    {
        float4 lw = *(const float4*)&ln_w[lane*4];
        float4 lb = *(const float4*)&ln_b[lane*4];
        float4 w0 = *(const float4*)&Wb[(4*lane+0)*NH];
        float4 w1 = *(const float4*)&Wb[(4*lane+1)*NH];
        float4 w2 = *(const float4*)&Wb[(4*lane+2)*NH];
        float4 w3 = *(const float4*)&Wb[(4*lane+3)*NH];
        #pragma unroll 2
        for (int rr=0; rr<8; rr++){
            int row = w*8 + rr;
            float4 x = *(const float4*)&z[(size_t)(p0+row)*DM + lane*4];
            float s  = x.x+x.y+x.z+x.w;
            float sq = x.x*x.x + x.y*x.y + x.z*x.z + x.w*x.w;
            #pragma unroll
            for (int o=16;o>0;o>>=1){
                s  += __shfl_xor_sync(0xffffffffu, s,  o);
                sq += __shfl_xor_sync(0xffffffffu, sq, o);
            }
            float mu   = s*(1.0f/DM);
            float var  = fmaxf(sq*(1.0f/DM) - mu*mu, 0.0f);
            float rstd = rsqrtf(var + 1e-5f);
            float4 zn;
            zn.x = (x.x-mu)*rstd*lw.x + lb.x;
            zn.y = (x.y-mu)*rstd*lw.y + lb.y;
            zn.z = (x.z-mu)*rstd*lw.z + lb.z;
            zn.w = (x.w-mu)*rstd*lw.w + lb.w;
            uint4 u = { f2tf(zn.x), f2tf(zn.y), f2tf(zn.z), f2tf(zn.w) };
            *(uint4*)&As[row*SA + lane*4] = u;
            float a0 = zn.x*w0.x + zn.y*w1.x + zn.z*w2.x + zn.w*w3.x;
            float a1 = zn.x*w0.y + zn.y*w1.y + zn.z*w2.y + zn.w*w3.y;
            float a2 = zn.x*w0.z + zn.y*w1.z + zn.z*w2.z + zn.w*w3.z;
            float a3 = zn.x*w0.w + zn.y*w1.w + zn.z*w2.w + zn.w*w3.w;
            #pragma unroll
            for (int o=16;o>0;o>>=1){
                a0 += __shfl_xor_sync(0xffffffffu, a0, o);
                a1 += __shfl_xor_sync(0xffffffffu, a1, o);
                a2 += __shfl_xor_sync(0xffffffffu, a2, o);
                a3 += __shfl_xor_sync(0xffffffffu, a3, o);
            }
            if (lane==0){
                g_biasT[0*NP + p0+row] = a0;
                g_biasT[1*NP + p0+row] = a1;
                g_biasT[2*NP + p0+row] = a2;
                g_biasT[3*NP + p0+row] = a3;
            }
        }
    }

    // ---- 4 projections reuse the A tile ----
    #pragma unroll 1
    for (int mode=0; mode<4; mode++){
        const float* W = (mode==0)?Wq:(mode==1)?Wk:(mode==2)?Wv:Wg;
        float* O = (mode==0)?g_q:(mode==1)?g_k:(mode==2)?g_v:g_gate;
        __syncthreads();
        for (int e = tid; e < 128*32; e += 512){
            int row = e>>5, c4 = e&31;
            float4 v = *(const float4*)&W[row*DM + c4*4];
            uint4 u = { f2tf(v.x), f2tf(v.y), f2tf(v.z), f2tf(v.w) };
            *(uint4*)&Ws[row*SB + c4*4] = u;
        }
        __syncthreads();

        float acc[2][4][4];
        #pragma unroll
        for (int mt=0;mt<2;mt++)
            #pragma unroll
            for (int nt=0;nt<4;nt++)
                #pragma unroll
                for (int u=0;u<4;u++) acc[mt][nt][u]=0.f;

        gemm_warp16(As, Ws, acc, wm, wn, g, t4);

        #pragma unroll
        for (int mt=0;mt<2;mt++)
            #pragma unroll
            for (int nt=0;nt<4;nt++){
                int col = wn*32 + nt*8 + 2*t4;
                #pragma unroll
                for (int rp=0;rp<2;rp++){
                    int row = p0 + wm*32 + mt*16 + g + 8*rp;
                    float v0 = acc[mt][nt][2*rp], v1 = acc[mt][nt][2*rp+1];
                    if (mode==3){
                        v0 = 1.f/(1.f + __expf(-(v0 + bg[col])));
                        v1 = 1.f/(1.f + __expf(-(v1 + bg[col+1])));
                    }
                    float2 o2 = {v0, v1};
                    *(float2*)&O[(size_t)row*DM + col] = o2;
                }
            }
    }
}

// ---------------------------------------------------------------------------
// Kernel 3: output GEMM out = g_att @ Wo + bo (512 thr, 16 warps)
// ---------------------------------------------------------------------------
__global__ __launch_bounds__(512,1) void k_out(const float* __restrict__ Wo,
                                               const float* __restrict__ bo,
                                               float* __restrict__ dout)
{
    extern __shared__ unsigned sm[];
    unsigned* As = sm;
    unsigned* Ws = sm + 128*SA;
    int tid = threadIdx.x;
    int w = tid>>5, lane = tid&31, g = lane>>2, t4 = lane&3;
    int wm = w>>2, wn = w&3;

    const float* Ab = g_att + (size_t)blockIdx.x*128*DM;
    for (int e = tid; e < 128*32; e += 512){
        int row = e>>5, c4 = e&31;
        float4 v = *(const float4*)&Ab[row*DM + c4*4];
        uint4 u = { f2tf(v.x), f2tf(v.y), f2tf(v.z), f2tf(v.w) };
        *(uint4*)&As[row*SA + c4*4] = u;
        float4 wv = *(const float4*)&Wo[row*DM + c4*4];
        uint4 wu = { f2tf(wv.x), f2tf(wv.y), f2tf(wv.z), f2tf(wv.w) };
        *(uint4*)&Ws[row*SB + c4*4] = wu;
    }
    __syncthreads();

    float acc[2][4][4];
    #pragma unroll
    for (int mt=0;mt<2;mt++)
        #pragma unroll
        for (int nt=0;nt<4;nt++)
            #pragma unroll
            for (int u=0;u<4;u++) acc[mt][nt][u]=0.f;

    gemm_warp16(As, Ws, acc, wm, wn, g, t4);

    #pragma unroll
    for (int mt=0;mt<2;mt++)
        #pragma unroll
        for (int nt=0;nt<4;nt++){
            int col = wn*32 + nt*8 + 2*t4;
            #pragma unroll
            for (int rp=0;rp<2;rp++){
                int row = blockIdx.x*128 + wm*32 + mt*16 + g + 8*rp;
                float2 o2 = { acc[mt][nt][2*rp] + bo[col],
                              acc[mt][nt][2*rp+1] + bo[col+1] };
                *(float2*)&dout[(size_t)row*DM + col] = o2;
            }
        }
}

// ---------------------------------------------------------------------------
// Kernel 2: tensor-core attention per (row r, head h). 512 thr, 16 warps,
// warp owns 16 query rows. No-max softmax (logits bounded), mask kept.
// ---------------------------------------------------------------------------
__global__ __launch_bounds__(512,1) void k_attn(const float* __restrict__ mask)
{
    extern __shared__ unsigned sm[];
    unsigned* Qs = sm;                      // 256*SQ
    unsigned* Ks = Qs + 256*SQ;
    unsigned* Vs = Ks + 256*SQ;             // 256*SV
    unsigned* Ps = Vs + 256*SV;             // 256*SP
    float*   msk = (float*)(Ps + 256*SP);   // 256

    int r = blockIdx.x, h = blockIdx.y;
    int tid = threadIdx.x;
    int w = tid>>5, lane = tid&31, g = lane>>2, t4 = lane&3;
    const float rscale = 0.17677669529663687f; // 1/sqrt(32)

    for (int e = tid; e < 256*8; e += 512){
        int row = e>>3, c4 = e&7;
        size_t gi = (size_t)(r*L + row)*DM + h*DK + c4*4;
        float4 q4 = *(const float4*)&g_q[gi];
        float4 k4 = *(const float4*)&g_k[gi];
        float4 v4 = *(const float4*)&g_v[gi];
        uint4 qu = { f2tf(q4.x), f2tf(q4.y), f2tf(q4.z), f2tf(q4.w) };
        uint4 ku = { f2tf(k4.x), f2tf(k4.y), f2tf(k4.z), f2tf(k4.w) };
        uint4 vu = { f2tf(v4.x), f2tf(v4.y), f2tf(v4.z), f2tf(v4.w) };
        *(uint4*)&Qs[row*SQ + c4*4] = qu;
        *(uint4*)&Ks[row*SQ + c4*4] = ku;
        *(uint4*)&Vs[row*SV + c4*4] = vu;
    }
    if (tid < 256) msk[tid] = mask[tid];
    __syncthreads();

    int rb = w*16;
    // Q fragments in registers (warp-private rows)
    unsigned qa[4][4];
    #pragma unroll
    for (int ks=0; ks<4; ks++){
        int k0 = ks*8;
        qa[ks][0] = Qs[(rb+g  )*SQ + k0 + t4];
        qa[ks][1] = Qs[(rb+g+8)*SQ + k0 + t4];
        qa[ks][2] = Qs[(rb+g  )*SQ + k0 + t4 + 4];
        qa[ks][3] = Qs[(rb+g+8)*SQ + k0 + t4 + 4];
    }
    float mi0 = msk[rb+g], mi1 = msk[rb+g+8];
    float ssum[2] = {0.f, 0.f};
    float oacc[4][4];
    #pragma unroll
    for (int nt=0;nt<4;nt++)
        #pragma unroll
        for (int u=0;u<4;u++) oacc[nt][u]=0.f;

    #pragma unroll 1
    for (int jt=0; jt<4; jt++){
        int jb = jt*64;
        float sacc[8][4];
        #pragma unroll
        for (int nt=0;nt<8;nt++)
            #pragma unroll
            for (int u=0;u<4;u++) sacc[nt][u]=0.f;
        #pragma unroll
        for (int ks=0; ks<4; ks++){
            int k0 = ks*8;
            unsigned b[8][2];
            #pragma unroll
            for (int nt=0;nt<8;nt++){
                int jr = jb + nt*8 + g;
                b[nt][0] = Ks[jr*SQ + k0 + t4];
                b[nt][1] = Ks[jr*SQ + k0 + t4 + 4];
            }
            #pragma unroll
            for (int nt=0;nt<8;nt++)
                mma8(sacc[nt], qa[ks], b[nt]);
        }
        // bias + mask + exp (no max subtraction: logits bounded), stage P
        float psum[2] = {0.f, 0.f};
        #pragma unroll
        for (int nt=0;nt<8;nt++){
            int j0 = jb + nt*8 + 2*t4;
            float mj0 = msk[j0], mj1 = msk[j0+1];
            #pragma unroll
            for (int rp=0;rp<2;rp++){
                int i = rb + g + 8*rp;
                float mi = rp ? mi1 : mi0;
                float2 bi = *(const float2*)&g_biasT[h*NP + i*L + j0];
                float s0 = sacc[nt][2*rp]  *rscale + bi.x;
                float s1 = sacc[nt][2*rp+1]*rscale + bi.y;
                float p0 = (mi*mj0 > 0.f) ? __expf(s0) : 0.f;
                float p1 = (mi*mj1 > 0.f) ? __expf(s1) : 0.f;
                psum[rp] += p0 + p1;
                uint2 pu = { f2tf(p0), f2tf(p1) };
                *(uint2*)&Ps[i*SP + nt*8 + 2*t4] = pu;
            }
        }
        #pragma unroll
        for (int rp=0;rp<2;rp++){
            float s = psum[rp];
            s += __shfl_xor_sync(0xffffffffu, s, 1);
            s += __shfl_xor_sync(0xffffffffu, s, 2);
            ssum[rp] += s;
        }
        __syncwarp();
        // O += P @ V
        #pragma unroll
        for (int kc=0; kc<8; kc++){
            int k0 = kc*8;
            unsigned a[4];
            a[0] = Ps[(rb+g  )*SP + k0 + t4];
            a[1] = Ps[(rb+g+8)*SP + k0 + t4];
            a[2] = Ps[(rb+g  )*SP + k0 + t4 + 4];
            a[3] = Ps[(rb+g+8)*SP + k0 + t4 + 4];
            unsigned b[4][2];
            #pragma unroll
            for (int nt=0;nt<4;nt++){
                b[nt][0] = Vs[(jb+k0+t4  )*SV + nt*8 + g];
                b[nt][1] = Vs[(jb+k0+t4+4)*SV + nt*8 + g];
            }
            #pragma unroll
            for (int nt=0;nt<4;nt++)
                mma8(oacc[nt], a, b[nt]);
        }
        __syncwarp();
    }
    // epilogue: normalize, gate, store
    float rinv[2] = { 1.f/ssum[0], 1.f/ssum[1] };
    #pragma unroll
    for (int nt=0;nt<4;nt++)
        #pragma unroll
        for (int rp=0;rp<2;rp++){
            int i = rb + g + 8*rp;
            int d = nt*8 + 2*t4;
            size_t gi = (size_t)(r*L + i)*DM + h*DK + d;
            float2 gt = *(const float2*)&g_gate[gi];
            float2 o2 = { oacc[nt][2*rp]  *rinv[rp]*gt.x,
                          oacc[nt][2*rp+1]*rinv[rp]*gt.y };
            *(float2*)&g_att[gi] = o2;
        }
}

// ---------------------------------------------------------------------------
extern "C" void kernel_launch(void* const* d_in, const int* in_sizes, int n_in,
                              void* d_out, int out_size)
{
    const float* z    = (const float*)d_in[0];
    const float* mask = (const float*)d_in[1];
    const float* ln_w = (const float*)d_in[2];
    const float* ln_b = (const float*)d_in[3];
    const float* Wq   = (const float*)d_in[4];
    const float* Wk   = (const float*)d_in[5];
    const float* Wv   = (const float*)d_in[6];
    const float* Wb   = (const float*)d_in[7];
    const float* Wg   = (const float*)d_in[8];
    const float* bg   = (const float*)d_in[9];
    const float* Wo   = (const float*)d_in[10];
    const float* bo   = (const float*)d_in[11];
    float* out = (float*)d_out;

    const int GEMM_SMEM = (128*SA + 128*SB)*4;                          // 137216
    const int ATT_SMEM  = (256*SQ + 256*SQ + 256*SV + 256*SP + 256)*4;  // 185344
    cudaFuncSetAttribute(k_qkvg, cudaFuncAttributeMaxDynamicSharedMemorySize, GEMM_SMEM);
    cudaFuncSetAttribute(k_out,  cudaFuncAttributeMaxDynamicSharedMemorySize, GEMM_SMEM);
    cudaFuncSetAttribute(k_attn, cudaFuncAttributeMaxDynamicSharedMemorySize, ATT_SMEM);

    k_qkvg<<<NP/128, 512, GEMM_SMEM>>>(z, ln_w, ln_b, Wb, Wq, Wk, Wv, Wg, bg);
    k_attn<<<dim3(L, NH), 512, ATT_SMEM>>>(mask);
    k_out <<<NP/128, 512, GEMM_SMEM>>>(Wo, bo, out);
}

// round 6
// speedup vs baseline: 3.9397x; 1.5204x over previous
#include <cuda_runtime.h>
#include <cuda_fp16.h>
#include <math.h>
#include <stdint.h>

#define L   256
#define DM  128
#define NH  4
#define DK  32
#define NP  (L*L)
#define WS  136   // GEMM tile stride (halves): 272B rows -> conflict-free ldmatrix
#define AS  40    // attention tile stride (halves): 80B rows -> conflict-free

__device__ __align__(16) __half g_q[NP*DM];
__device__ __align__(16) __half g_k[NP*DM];
__device__ __align__(16) __half g_v[NP*DM];
__device__ __align__(16) __half g_gate[NP*DM];
__device__ __align__(16) __half g_att[NP*DM];
__device__ float g_biasT[NH*NP];                 // [h][i*L+j]
__device__ __align__(16) __half g_wT[5*128*WS];  // padded half W images: q,k,v,g,o

__device__ __forceinline__ uint32_t smem_u32(const void* p){
    uint32_t a;
    asm("{ .reg .u64 t; cvta.to.shared.u64 t, %1; cvt.u32.u64 %0, t; }" : "=r"(a) : "l"(p));
    return a;
}
__device__ __forceinline__ void mma16(float* c, const uint32_t* a, const uint32_t* b){
    asm volatile("mma.sync.aligned.m16n8k16.row.col.f32.f16.f16.f32 "
        "{%0,%1,%2,%3}, {%4,%5,%6,%7}, {%8,%9}, {%0,%1,%2,%3};\n"
        : "+f"(c[0]), "+f"(c[1]), "+f"(c[2]), "+f"(c[3])
        : "r"(a[0]), "r"(a[1]), "r"(a[2]), "r"(a[3]), "r"(b[0]), "r"(b[1]));
}
__device__ __forceinline__ void ldsm4(uint32_t* r, uint32_t a){
    asm volatile("ldmatrix.sync.aligned.m8n8.x4.shared.b16 {%0,%1,%2,%3}, [%4];"
        : "=r"(r[0]), "=r"(r[1]), "=r"(r[2]), "=r"(r[3]) : "r"(a));
}
__device__ __forceinline__ void ldsm4t(uint32_t* r, uint32_t a){
    asm volatile("ldmatrix.sync.aligned.m8n8.x4.trans.shared.b16 {%0,%1,%2,%3}, [%4];"
        : "=r"(r[0]), "=r"(r[1]), "=r"(r[2]), "=r"(r[3]) : "r"(a));
}
__device__ __forceinline__ uint32_t h2u(__half2 h){ return *(uint32_t*)&h; }

// ---------------------------------------------------------------------------
// K0: convert weights to padded half images [k=128][WS] (row-major, n cols)
// ---------------------------------------------------------------------------
__global__ __launch_bounds__(512) void k_prep(const float* __restrict__ Wq,
    const float* __restrict__ Wk, const float* __restrict__ Wv,
    const float* __restrict__ Wg, const float* __restrict__ Wo)
{
    int m = blockIdx.x;
    const float* W = (m==0)?Wq:(m==1)?Wk:(m==2)?Wv:(m==3)?Wg:Wo;
    __half* dst = g_wT + m*128*WS;
    for (int e = threadIdx.x; e < 128*32; e += 512){
        int k = e>>5, c4 = e&31;
        float4 v = *(const float4*)&W[k*128 + c4*4];
        uint2 u = { h2u(__floats2half2_rn(v.x, v.y)), h2u(__floats2half2_rn(v.z, v.w)) };
        *(uint2*)&dst[k*WS + c4*4] = u;
    }
}

// ---------------------------------------------------------------------------
// K1: LN + biasT + q/k/v/gate projections (fp16 mma + ldmatrix)
// ---------------------------------------------------------------------------
__global__ __launch_bounds__(512,1) void k_qkvg(const float* __restrict__ z,
    const float* __restrict__ ln_w, const float* __restrict__ ln_b,
    const float* __restrict__ Wb, const float* __restrict__ bg)
{
    extern __shared__ char smem[];
    __half* At = (__half*)smem;                      // 128*WS halves
    __half* Wall = (__half*)(smem + 128*WS*2);       // 4 * 128*WS halves
    uint32_t sAt = smem_u32(At), sW = smem_u32(Wall);
    int tid = threadIdx.x, w = tid>>5, lane = tid&31, g = lane>>2, t4 = lane&3;
    int wm = w>>2, wn = w&3;
    int p0 = blockIdx.x*128;

    { // LayerNorm -> half A tile + bias projection
        float4 lw = *(const float4*)&ln_w[lane*4];
        float4 lb = *(const float4*)&ln_b[lane*4];
        float4 w0 = *(const float4*)&Wb[(4*lane+0)*NH];
        float4 w1 = *(const float4*)&Wb[(4*lane+1)*NH];
        float4 w2 = *(const float4*)&Wb[(4*lane+2)*NH];
        float4 w3 = *(const float4*)&Wb[(4*lane+3)*NH];
        #pragma unroll 2
        for (int rr=0; rr<8; rr++){
            int row = w*8 + rr;
            float4 x = *(const float4*)&z[(size_t)(p0+row)*DM + lane*4];
            float s = x.x+x.y+x.z+x.w;
            float sq = x.x*x.x + x.y*x.y + x.z*x.z + x.w*x.w;
            #pragma unroll
            for (int o=16;o>0;o>>=1){
                s  += __shfl_xor_sync(0xffffffffu, s,  o);
                sq += __shfl_xor_sync(0xffffffffu, sq, o);
            }
            float mu = s*(1.0f/DM);
            float var = fmaxf(sq*(1.0f/DM) - mu*mu, 0.0f);
            float rstd = rsqrtf(var + 1e-5f);
            float4 zn;
            zn.x=(x.x-mu)*rstd*lw.x+lb.x; zn.y=(x.y-mu)*rstd*lw.y+lb.y;
            zn.z=(x.z-mu)*rstd*lw.z+lb.z; zn.w=(x.w-mu)*rstd*lw.w+lb.w;
            uint2 u = { h2u(__floats2half2_rn(zn.x, zn.y)), h2u(__floats2half2_rn(zn.z, zn.w)) };
            *(uint2*)&At[row*WS + lane*4] = u;
            float a0 = zn.x*w0.x+zn.y*w1.x+zn.z*w2.x+zn.w*w3.x;
            float a1 = zn.x*w0.y+zn.y*w1.y+zn.z*w2.y+zn.w*w3.y;
            float a2 = zn.x*w0.z+zn.y*w1.z+zn.z*w2.z+zn.w*w3.z;
            float a3 = zn.x*w0.w+zn.y*w1.w+zn.z*w2.w+zn.w*w3.w;
            #pragma unroll
            for (int o=16;o>0;o>>=1){
                a0 += __shfl_xor_sync(0xffffffffu, a0, o);
                a1 += __shfl_xor_sync(0xffffffffu, a1, o);
                a2 += __shfl_xor_sync(0xffffffffu, a2, o);
                a3 += __shfl_xor_sync(0xffffffffu, a3, o);
            }
            if (lane==0){
                g_biasT[0*NP+p0+row]=a0; g_biasT[1*NP+p0+row]=a1;
                g_biasT[2*NP+p0+row]=a2; g_biasT[3*NP+p0+row]=a3;
            }
        }
    }
    // stage all 4 weight tiles (pure copy: 8704 uint4)
    for (int e = tid; e < 4*128*WS/8; e += 512)
        ((uint4*)Wall)[e] = ((const uint4*)g_wT)[e];
    __syncthreads();

    int rb = wm*32;
    #pragma unroll 1
    for (int mode=0; mode<4; mode++){
        uint32_t sWm = sW + mode*(128*WS*2);
        __half* O = (mode==0)?g_q:(mode==1)?g_k:(mode==2)?g_v:g_gate;
        float acc[2][4][4];
        #pragma unroll
        for (int mt=0;mt<2;mt++)
            #pragma unroll
            for (int nt=0;nt<4;nt++)
                #pragma unroll
                for (int u=0;u<4;u++) acc[mt][nt][u]=0.f;
        #pragma unroll
        for (int kc=0; kc<8; kc++){
            int k0 = kc*16;
            uint32_t a[2][4];
            #pragma unroll
            for (int mt=0;mt<2;mt++)
                ldsm4(a[mt], sAt + ((rb + mt*16 + (lane&15))*WS + k0 + ((lane>>4)<<3))*2);
            uint32_t b[4][4];
            #pragma unroll
            for (int pr=0;pr<2;pr++)
                ldsm4t(b[2*pr], sWm + ((k0 + (lane&7) + (((lane>>3)&1)<<3))*WS
                                        + wn*32 + pr*16 + ((lane>>4)<<3))*2);
            #pragma unroll
            for (int mt=0;mt<2;mt++)
                #pragma unroll
                for (int nt=0;nt<4;nt++)
                    mma16(acc[mt][nt], a[mt], &b[nt&~1][(nt&1)*2]);
        }
        #pragma unroll
        for (int mt=0;mt<2;mt++)
            #pragma unroll
            for (int nt=0;nt<4;nt++){
                int col = wn*32 + nt*8 + 2*t4;
                #pragma unroll
                for (int rp=0;rp<2;rp++){
                    int row = p0 + rb + mt*16 + g + 8*rp;
                    float v0 = acc[mt][nt][2*rp], v1 = acc[mt][nt][2*rp+1];
                    if (mode==3){
                        v0 = 1.f/(1.f + __expf(-(v0 + bg[col])));
                        v1 = 1.f/(1.f + __expf(-(v1 + bg[col+1])));
                    }
                    *(__half2*)&O[(size_t)row*DM + col] = __floats2half2_rn(v0, v1);
                }
            }
    }
}

// ---------------------------------------------------------------------------
// K3: out = g_att @ Wo + bo
// ---------------------------------------------------------------------------
__global__ __launch_bounds__(512,1) void k_out(const float* __restrict__ bo,
                                               float* __restrict__ dout)
{
    extern __shared__ char smem[];
    __half* At = (__half*)smem;
    __half* Ws = (__half*)(smem + 128*WS*2);
    uint32_t sAt = smem_u32(At), sW = smem_u32(Ws);
    int tid = threadIdx.x, w = tid>>5, lane = tid&31, g = lane>>2, t4 = lane&3;
    int wm = w>>2, wn = w&3;
    int p0 = blockIdx.x*128;

    for (int e = tid; e < 2048; e += 512){          // A restride copy
        int row = e>>4, c = e&15;
        ((uint4*)At)[row*17 + c] = ((const uint4*)g_att)[(size_t)(p0+row)*16 + c];
    }
    for (int e = tid; e < 128*WS/8; e += 512)       // Wo copy
        ((uint4*)Ws)[e] = ((const uint4*)(g_wT + 4*128*WS))[e];
    __syncthreads();

    int rb = wm*32;
    float acc[2][4][4];
    #pragma unroll
    for (int mt=0;mt<2;mt++)
        #pragma unroll
        for (int nt=0;nt<4;nt++)
            #pragma unroll
            for (int u=0;u<4;u++) acc[mt][nt][u]=0.f;
    #pragma unroll
    for (int kc=0; kc<8; kc++){
        int k0 = kc*16;
        uint32_t a[2][4];
        #pragma unroll
        for (int mt=0;mt<2;mt++)
            ldsm4(a[mt], sAt + ((rb + mt*16 + (lane&15))*WS + k0 + ((lane>>4)<<3))*2);
        uint32_t b[4][4];
        #pragma unroll
        for (int pr=0;pr<2;pr++)
            ldsm4t(b[2*pr], sW + ((k0 + (lane&7) + (((lane>>3)&1)<<3))*WS
                                   + wn*32 + pr*16 + ((lane>>4)<<3))*2);
        #pragma unroll
        for (int mt=0;mt<2;mt++)
            #pragma unroll
            for (int nt=0;nt<4;nt++)
                mma16(acc[mt][nt], a[mt], &b[nt&~1][(nt&1)*2]);
    }
    #pragma unroll
    for (int mt=0;mt<2;mt++)
        #pragma unroll
        for (int nt=0;nt<4;nt++){
            int col = wn*32 + nt*8 + 2*t4;
            #pragma unroll
            for (int rp=0;rp<2;rp++){
                int row = p0 + rb + mt*16 + g + 8*rp;
                float2 o2 = { acc[mt][nt][2*rp] + bo[col],
                              acc[mt][nt][2*rp+1] + bo[col+1] };
                *(float2*)&dout[(size_t)row*DM + col] = o2;
            }
        }
}

// ---------------------------------------------------------------------------
// K2: attention per (r,h). 16 warps x 16 query rows. fp16 mma, P stays in regs.
// ---------------------------------------------------------------------------
__global__ __launch_bounds__(512,1) void k_attn(const float* __restrict__ mask)
{
    extern __shared__ char smem[];
    __half* Qs = (__half*)smem;                 // 256*AS
    __half* Ks = Qs + 256*AS;
    __half* Vs = Ks + 256*AS;
    float* msk = (float*)(Vs + 256*AS);
    uint32_t sQ = smem_u32(Qs), sK = smem_u32(Ks), sV = smem_u32(Vs);
    int r = blockIdx.x, h = blockIdx.y;
    int tid = threadIdx.x, w = tid>>5, lane = tid&31, g = lane>>2, t4 = lane&3;
    const float rscale = 0.17677669529663687f;

    for (int e = tid; e < 1024; e += 512){
        int row = e>>2, c = e&3;
        size_t gi = ((size_t)(r*L + row)*DM + h*DK)>>3;
        ((uint4*)Qs)[row*5 + c] = ((const uint4*)g_q)[gi + c];
        ((uint4*)Ks)[row*5 + c] = ((const uint4*)g_k)[gi + c];
        ((uint4*)Vs)[row*5 + c] = ((const uint4*)g_v)[gi + c];
    }
    if (tid < 256) msk[tid] = mask[tid];
    __syncthreads();

    int rb = w*16;
    uint32_t qa[2][4];
    #pragma unroll
    for (int kc=0;kc<2;kc++)
        ldsm4(qa[kc], sQ + ((rb + (lane&15))*AS + kc*16 + ((lane>>4)<<3))*2);

    float mi0 = msk[rb+g], mi1 = msk[rb+g+8];
    float ssum[2] = {0.f, 0.f};
    float oacc[4][4];
    #pragma unroll
    for (int nt=0;nt<4;nt++)
        #pragma unroll
        for (int u=0;u<4;u++) oacc[nt][u]=0.f;

    #pragma unroll 1
    for (int jt=0; jt<4; jt++){
        int jb = jt*64;
        float sacc[8][4];
        #pragma unroll
        for (int nt=0;nt<8;nt++)
            #pragma unroll
            for (int u=0;u<4;u++) sacc[nt][u]=0.f;
        #pragma unroll
        for (int kc=0;kc<2;kc++){
            #pragma unroll
            for (int pr=0;pr<4;pr++){
                uint32_t b[4];
                ldsm4(b, sK + ((jb + pr*16 + (lane&7) + ((lane>>4)<<3))*AS
                                + kc*16 + (((lane>>3)&1)<<3))*2);
                mma16(sacc[2*pr],   qa[kc], &b[0]);
                mma16(sacc[2*pr+1], qa[kc], &b[2]);
            }
        }
        // bias + mask + exp; pack P into A-fragments (no smem)
        uint32_t ph[8][2];
        float psum[2] = {0.f, 0.f};
        #pragma unroll
        for (int nt=0;nt<8;nt++){
            int j0 = jb + nt*8 + 2*t4;
            float mj0 = msk[j0], mj1 = msk[j0+1];
            #pragma unroll
            for (int rp=0;rp<2;rp++){
                int i = rb + g + 8*rp;
                float mi = rp ? mi1 : mi0;
                float2 bi = *(const float2*)&g_biasT[h*NP + i*L + j0];
                float s0 = sacc[nt][2*rp]  *rscale + bi.x;
                float s1 = sacc[nt][2*rp+1]*rscale + bi.y;
                float p0 = (mi*mj0 > 0.f) ? __expf(s0) : 0.f;
                float p1 = (mi*mj1 > 0.f) ? __expf(s1) : 0.f;
                psum[rp] += p0 + p1;
                ph[nt][rp] = h2u(__floats2half2_rn(p0, p1));
            }
        }
        #pragma unroll
        for (int rp=0;rp<2;rp++){
            float s = psum[rp];
            s += __shfl_xor_sync(0xffffffffu, s, 1);
            s += __shfl_xor_sync(0xffffffffu, s, 2);
            ssum[rp] += s;
        }
        // O += P @ V
        #pragma unroll
        for (int kc2=0;kc2<4;kc2++){
            uint32_t pa[4] = { ph[2*kc2][0], ph[2*kc2][1], ph[2*kc2+1][0], ph[2*kc2+1][1] };
            #pragma unroll
            for (int pr=0;pr<2;pr++){
                uint32_t b[4];
                ldsm4t(b, sV + ((jb + kc2*16 + (lane&7) + (((lane>>3)&1)<<3))*AS
                                 + pr*16 + ((lane>>4)<<3))*2);
                mma16(oacc[2*pr],   pa, &b[0]);
                mma16(oacc[2*pr+1], pa, &b[2]);
            }
        }
    }
    // epilogue: normalize, gate, store half
    float rinv[2] = { 1.f/ssum[0], 1.f/ssum[1] };
    #pragma unroll
    for (int nt=0;nt<4;nt++)
        #pragma unroll
        for (int rp=0;rp<2;rp++){
            int i = rb + g + 8*rp;
            int d = nt*8 + 2*t4;
            size_t gi = (size_t)(r*L + i)*DM + h*DK + d;
            float2 gf = __half22float2(*(__half2*)&g_gate[gi]);
            *(__half2*)&g_att[gi] = __floats2half2_rn(
                oacc[nt][2*rp]  *rinv[rp]*gf.x,
                oacc[nt][2*rp+1]*rinv[rp]*gf.y);
        }
}

// ---------------------------------------------------------------------------
extern "C" void kernel_launch(void* const* d_in, const int* in_sizes, int n_in,
                              void* d_out, int out_size)
{
    const float* z    = (const float*)d_in[0];
    const float* mask = (const float*)d_in[1];
    const float* ln_w = (const float*)d_in[2];
    const float* ln_b = (const float*)d_in[3];
    const float* Wq   = (const float*)d_in[4];
    const float* Wk   = (const float*)d_in[5];
    const float* Wv   = (const float*)d_in[6];
    const float* Wb   = (const float*)d_in[7];
    const float* Wg   = (const float*)d_in[8];
    const float* bg   = (const float*)d_in[9];
    const float* Wo   = (const float*)d_in[10];
    const float* bo   = (const float*)d_in[11];
    float* out = (float*)d_out;

    const int QK_SMEM  = 5*128*WS*2;                 // 174080
    const int OUT_SMEM = 2*128*WS*2;                 // 69632
    const int ATT_SMEM = 3*256*AS*2 + 256*4;         // 62464
    cudaFuncSetAttribute(k_qkvg, cudaFuncAttributeMaxDynamicSharedMemorySize, QK_SMEM);
    cudaFuncSetAttribute(k_out,  cudaFuncAttributeMaxDynamicSharedMemorySize, OUT_SMEM);
    cudaFuncSetAttribute(k_attn, cudaFuncAttributeMaxDynamicSharedMemorySize, ATT_SMEM);

    k_prep<<<5, 512>>>(Wq, Wk, Wv, Wg, Wo);
    k_qkvg<<<NP/128, 512, QK_SMEM>>>(z, ln_w, ln_b, Wb, bg);
    k_attn<<<dim3(L, NH), 512, ATT_SMEM>>>(mask);
    k_out <<<NP/128, 512, OUT_SMEM>>>(bo, out);
}

// round 7
// speedup vs baseline: 4.1439x; 1.0518x over previous
#include <cuda_runtime.h>
#include <cuda_fp16.h>
#include <math.h>
#include <stdint.h>

#define L   256
#define DM  128
#define NH  4
#define DK  32
#define NP  (L*L)
#define WS  136   // big-tile stride (halves)
#define AS  40    // small-tile stride (halves)

__device__ __align__(16) __half g_att[NP*DM];
__device__ float g_biasT[NH*NP];                 // [h][i*L+j]
__device__ __align__(16) __half g_wT[5*128*WS];  // half W images [k][n], padded

__device__ __forceinline__ uint32_t smem_u32(const void* p){
    uint32_t a;
    asm("{ .reg .u64 t; cvta.to.shared.u64 t, %1; cvt.u32.u64 %0, t; }" : "=r"(a) : "l"(p));
    return a;
}
__device__ __forceinline__ void mma16(float* c, const uint32_t* a, const uint32_t* b){
    asm volatile("mma.sync.aligned.m16n8k16.row.col.f32.f16.f16.f32 "
        "{%0,%1,%2,%3}, {%4,%5,%6,%7}, {%8,%9}, {%0,%1,%2,%3};\n"
        : "+f"(c[0]), "+f"(c[1]), "+f"(c[2]), "+f"(c[3])
        : "r"(a[0]), "r"(a[1]), "r"(a[2]), "r"(a[3]), "r"(b[0]), "r"(b[1]));
}
__device__ __forceinline__ void ldsm4(uint32_t* r, uint32_t a){
    asm volatile("ldmatrix.sync.aligned.m8n8.x4.shared.b16 {%0,%1,%2,%3}, [%4];"
        : "=r"(r[0]), "=r"(r[1]), "=r"(r[2]), "=r"(r[3]) : "r"(a));
}
__device__ __forceinline__ void ldsm4t(uint32_t* r, uint32_t a){
    asm volatile("ldmatrix.sync.aligned.m8n8.x4.trans.shared.b16 {%0,%1,%2,%3}, [%4];"
        : "=r"(r[0]), "=r"(r[1]), "=r"(r[2]), "=r"(r[3]) : "r"(a));
}
__device__ __forceinline__ uint32_t h2u(__half2 h){ return *(uint32_t*)&h; }

// ---------------------------------------------------------------------------
// K0: weights -> padded half images [k=128][WS]
// ---------------------------------------------------------------------------
__global__ __launch_bounds__(512) void k_prep(const float* __restrict__ Wq,
    const float* __restrict__ Wk, const float* __restrict__ Wv,
    const float* __restrict__ Wg, const float* __restrict__ Wo)
{
    int m = blockIdx.x;
    const float* W = (m==0)?Wq:(m==1)?Wk:(m==2)?Wv:(m==3)?Wg:Wo;
    __half* dst = g_wT + m*128*WS;
    for (int e = threadIdx.x; e < 128*32; e += 512){
        int k = e>>5, c4 = e&31;
        float4 v = *(const float4*)&W[k*128 + c4*4];
        uint2 u = { h2u(__floats2half2_rn(v.x, v.y)), h2u(__floats2half2_rn(v.z, v.w)) };
        *(uint2*)&dst[k*WS + c4*4] = u;
    }
}

// ---------------------------------------------------------------------------
// K1: bias table only: biasT[h][p] = LN(z_p) @ Wb[:,h]. 1 warp/position.
// ---------------------------------------------------------------------------
__global__ __launch_bounds__(256) void k_bias(const float* __restrict__ z,
    const float* __restrict__ ln_w, const float* __restrict__ ln_b,
    const float* __restrict__ Wb)
{
    int w = threadIdx.x>>5, lane = threadIdx.x&31;
    int p = blockIdx.x*8 + w;
    float4 x = *(const float4*)&z[(size_t)p*DM + lane*4];
    float s = x.x+x.y+x.z+x.w;
    float sq = x.x*x.x+x.y*x.y+x.z*x.z+x.w*x.w;
    #pragma unroll
    for (int o=16;o>0;o>>=1){
        s  += __shfl_xor_sync(0xffffffffu, s,  o);
        sq += __shfl_xor_sync(0xffffffffu, sq, o);
    }
    float mu = s*(1.0f/DM);
    float var = fmaxf(sq*(1.0f/DM) - mu*mu, 0.0f);
    float rstd = rsqrtf(var + 1e-5f);
    float4 lw = *(const float4*)&ln_w[lane*4];
    float4 lb = *(const float4*)&ln_b[lane*4];
    float zn0=(x.x-mu)*rstd*lw.x+lb.x, zn1=(x.y-mu)*rstd*lw.y+lb.y;
    float zn2=(x.z-mu)*rstd*lw.z+lb.z, zn3=(x.w-mu)*rstd*lw.w+lb.w;
    float4 w0 = *(const float4*)&Wb[(4*lane+0)*NH];
    float4 w1 = *(const float4*)&Wb[(4*lane+1)*NH];
    float4 w2 = *(const float4*)&Wb[(4*lane+2)*NH];
    float4 w3 = *(const float4*)&Wb[(4*lane+3)*NH];
    float a0 = zn0*w0.x+zn1*w1.x+zn2*w2.x+zn3*w3.x;
    float a1 = zn0*w0.y+zn1*w1.y+zn2*w2.y+zn3*w3.y;
    float a2 = zn0*w0.z+zn1*w1.z+zn2*w2.z+zn3*w3.z;
    float a3 = zn0*w0.w+zn1*w1.w+zn2*w2.w+zn3*w3.w;
    #pragma unroll
    for (int o=16;o>0;o>>=1){
        a0 += __shfl_xor_sync(0xffffffffu, a0, o);
        a1 += __shfl_xor_sync(0xffffffffu, a1, o);
        a2 += __shfl_xor_sync(0xffffffffu, a2, o);
        a3 += __shfl_xor_sync(0xffffffffu, a3, o);
    }
    if (lane==0){
        g_biasT[0*NP+p]=a0; g_biasT[1*NP+p]=a1;
        g_biasT[2*NP+p]=a2; g_biasT[3*NP+p]=a3;
    }
}

// ---------------------------------------------------------------------------
// K2: fused per-row: LN -> per-head q/k/v/gate GEMM (smem) -> attention -> g_att
// smem (bytes): As 69632 | Qt/Kt/Vt/Gt 4x20480 | Wsl 4x10240 | msk 1024
// ---------------------------------------------------------------------------
__global__ __launch_bounds__(512,1) void k_main(const float* __restrict__ z,
    const float* __restrict__ ln_w, const float* __restrict__ ln_b,
    const float* __restrict__ bg, const float* __restrict__ mask)
{
    extern __shared__ char smem[];
    __half* As = (__half*)smem;                         // 256 x WS
    __half* Qt = (__half*)(smem + 69632);               // 256 x AS
    __half* Kt = Qt + 256*AS;
    __half* Vt = Kt + 256*AS;
    __half* Gt = Vt + 256*AS;
    __half* Wsl = Gt + 256*AS;                          // 4 x 128 x AS
    float* msk = (float*)(smem + 192512);
    uint32_t sAs = smem_u32(As), sQ = smem_u32(Qt), sK = smem_u32(Kt),
             sV = smem_u32(Vt), sWsl = smem_u32(Wsl);
    int r = blockIdx.x;
    int tid = threadIdx.x, w = tid>>5, lane = tid&31, g = lane>>2, t4 = lane&3;
    const float rscale = 0.17677669529663687f;

    // ---- phase 0: LN of row r's 256 positions -> As tile ----
    {
        float4 lw = *(const float4*)&ln_w[lane*4];
        float4 lb = *(const float4*)&ln_b[lane*4];
        #pragma unroll 2
        for (int rr=0; rr<16; rr++){
            int row = w*16 + rr;
            float4 x = *(const float4*)&z[(size_t)(r*L+row)*DM + lane*4];
            float s = x.x+x.y+x.z+x.w;
            float sq = x.x*x.x+x.y*x.y+x.z*x.z+x.w*x.w;
            #pragma unroll
            for (int o=16;o>0;o>>=1){
                s  += __shfl_xor_sync(0xffffffffu, s,  o);
                sq += __shfl_xor_sync(0xffffffffu, sq, o);
            }
            float mu = s*(1.0f/DM);
            float var = fmaxf(sq*(1.0f/DM) - mu*mu, 0.0f);
            float rstd = rsqrtf(var + 1e-5f);
            float z0=(x.x-mu)*rstd*lw.x+lb.x, z1=(x.y-mu)*rstd*lw.y+lb.y;
            float z2=(x.z-mu)*rstd*lw.z+lb.z, z3=(x.w-mu)*rstd*lw.w+lb.w;
            uint2 u = { h2u(__floats2half2_rn(z0,z1)), h2u(__floats2half2_rn(z2,z3)) };
            *(uint2*)&As[row*WS + lane*4] = u;
        }
        if (tid < 256) msk[tid] = mask[tid];
    }

    #pragma unroll 1
    for (int h=0; h<NH; h++){
        __syncthreads();
        // ---- stage W head-slices: 4 matrices x 128 rows x 32 halves ----
        for (int e = tid; e < 2048; e += 512){
            int m = e>>9, k = (e>>2)&127, c = e&3;
            *((uint4*)&Wsl[m*128*AS + k*AS + c*8]) =
                *((const uint4*)&g_wT[m*128*WS + k*WS + h*32 + c*8]);
        }
        __syncthreads();
        // ---- projections: warp wm=w>>1 rows, wn=w&1 16-col half ----
        {
            int wm = w>>1, wn = w&1, rb = wm*32;
            #pragma unroll 1
            for (int mode=0; mode<4; mode++){
                uint32_t sWm = sWsl + mode*(128*AS*2);
                __half* Tt = (mode==0)?Qt:(mode==1)?Kt:(mode==2)?Vt:Gt;
                float acc[2][2][4];
                #pragma unroll
                for (int mt=0;mt<2;mt++)
                    #pragma unroll
                    for (int nt=0;nt<2;nt++)
                        #pragma unroll
                        for (int u=0;u<4;u++) acc[mt][nt][u]=0.f;
                #pragma unroll
                for (int kc=0; kc<8; kc++){
                    int k0 = kc*16;
                    uint32_t a[2][4];
                    #pragma unroll
                    for (int mt=0;mt<2;mt++)
                        ldsm4(a[mt], sAs + ((rb + mt*16 + (lane&15))*WS + k0 + ((lane>>4)<<3))*2);
                    uint32_t b[4];
                    ldsm4t(b, sWm + ((k0 + (lane&7) + (((lane>>3)&1)<<3))*AS
                                      + wn*16 + ((lane>>4)<<3))*2);
                    #pragma unroll
                    for (int mt=0;mt<2;mt++){
                        mma16(acc[mt][0], a[mt], &b[0]);
                        mma16(acc[mt][1], a[mt], &b[2]);
                    }
                }
                #pragma unroll
                for (int mt=0;mt<2;mt++)
                    #pragma unroll
                    for (int nt=0;nt<2;nt++){
                        int col = wn*16 + nt*8 + 2*t4;
                        #pragma unroll
                        for (int rp=0;rp<2;rp++){
                            int row = rb + mt*16 + g + 8*rp;
                            float v0 = acc[mt][nt][2*rp], v1 = acc[mt][nt][2*rp+1];
                            if (mode==3){
                                v0 = 1.f/(1.f + __expf(-(v0 + bg[h*32+col])));
                                v1 = 1.f/(1.f + __expf(-(v1 + bg[h*32+col+1])));
                            }
                            *(__half2*)&Tt[row*AS + col] = __floats2half2_rn(v0, v1);
                        }
                    }
            }
        }
        __syncthreads();
        // ---- attention for head h: warp owns 16 query rows ----
        {
            int rb = w*16;
            uint32_t qa[2][4];
            #pragma unroll
            for (int kc=0;kc<2;kc++)
                ldsm4(qa[kc], sQ + ((rb + (lane&15))*AS + kc*16 + ((lane>>4)<<3))*2);
            float mi0 = msk[rb+g], mi1 = msk[rb+g+8];
            float ssum[2] = {0.f, 0.f};
            float oacc[4][4];
            #pragma unroll
            for (int nt=0;nt<4;nt++)
                #pragma unroll
                for (int u=0;u<4;u++) oacc[nt][u]=0.f;

            #pragma unroll 1
            for (int jt=0; jt<4; jt++){
                int jb = jt*64;
                float sacc[8][4];
                #pragma unroll
                for (int nt=0;nt<8;nt++)
                    #pragma unroll
                    for (int u=0;u<4;u++) sacc[nt][u]=0.f;
                #pragma unroll
                for (int kc=0;kc<2;kc++){
                    #pragma unroll
                    for (int pr=0;pr<4;pr++){
                        uint32_t b[4];
                        ldsm4(b, sK + ((jb + pr*16 + (lane&7) + ((lane>>4)<<3))*AS
                                        + kc*16 + (((lane>>3)&1)<<3))*2);
                        mma16(sacc[2*pr],   qa[kc], &b[0]);
                        mma16(sacc[2*pr+1], qa[kc], &b[2]);
                    }
                }
                uint32_t ph[8][2];
                float psum[2] = {0.f, 0.f};
                #pragma unroll
                for (int nt=0;nt<8;nt++){
                    int j0 = jb + nt*8 + 2*t4;
                    float mj0 = msk[j0], mj1 = msk[j0+1];
                    #pragma unroll
                    for (int rp=0;rp<2;rp++){
                        int i = rb + g + 8*rp;
                        float mi = rp ? mi1 : mi0;
                        float2 bi = *(const float2*)&g_biasT[h*NP + i*L + j0];
                        float s0 = sacc[nt][2*rp]  *rscale + bi.x;
                        float s1 = sacc[nt][2*rp+1]*rscale + bi.y;
                        float p0 = (mi*mj0 > 0.f) ? __expf(s0) : 0.f;
                        float p1 = (mi*mj1 > 0.f) ? __expf(s1) : 0.f;
                        psum[rp] += p0 + p1;
                        ph[nt][rp] = h2u(__floats2half2_rn(p0, p1));
                    }
                }
                #pragma unroll
                for (int rp=0;rp<2;rp++){
                    float s = psum[rp];
                    s += __shfl_xor_sync(0xffffffffu, s, 1);
                    s += __shfl_xor_sync(0xffffffffu, s, 2);
                    ssum[rp] += s;
                }
                #pragma unroll
                for (int kc2=0;kc2<4;kc2++){
                    uint32_t pa[4] = { ph[2*kc2][0], ph[2*kc2][1], ph[2*kc2+1][0], ph[2*kc2+1][1] };
                    #pragma unroll
                    for (int pr=0;pr<2;pr++){
                        uint32_t b[4];
                        ldsm4t(b, sV + ((jb + kc2*16 + (lane&7) + (((lane>>3)&1)<<3))*AS
                                         + pr*16 + ((lane>>4)<<3))*2);
                        mma16(oacc[2*pr],   pa, &b[0]);
                        mma16(oacc[2*pr+1], pa, &b[2]);
                    }
                }
            }
            float rinv[2] = { 1.f/ssum[0], 1.f/ssum[1] };
            #pragma unroll
            for (int nt=0;nt<4;nt++)
                #pragma unroll
                for (int rp=0;rp<2;rp++){
                    int i = rb + g + 8*rp;
                    int d = nt*8 + 2*t4;
                    float2 gf = __half22float2(*(__half2*)&Gt[i*AS + d]);
                    *(__half2*)&g_att[(size_t)(r*L+i)*DM + h*DK + d] = __floats2half2_rn(
                        oacc[nt][2*rp]  *rinv[rp]*gf.x,
                        oacc[nt][2*rp+1]*rinv[rp]*gf.y);
                }
        }
    }
}

// ---------------------------------------------------------------------------
// K3: out = g_att @ Wo + bo (unchanged from Round 6)
// ---------------------------------------------------------------------------
__global__ __launch_bounds__(512,1) void k_out(const float* __restrict__ bo,
                                               float* __restrict__ dout)
{
    extern __shared__ char smem[];
    __half* At = (__half*)smem;
    __half* Ws = (__half*)(smem + 128*WS*2);
    uint32_t sAt = smem_u32(At), sW = smem_u32(Ws);
    int tid = threadIdx.x, w = tid>>5, lane = tid&31, g = lane>>2, t4 = lane&3;
    int wm = w>>2, wn = w&3;
    int p0 = blockIdx.x*128;

    for (int e = tid; e < 2048; e += 512){
        int row = e>>4, c = e&15;
        ((uint4*)At)[row*17 + c] = ((const uint4*)g_att)[(size_t)(p0+row)*16 + c];
    }
    for (int e = tid; e < 128*WS/8; e += 512)
        ((uint4*)Ws)[e] = ((const uint4*)(g_wT + 4*128*WS))[e];
    __syncthreads();

    int rb = wm*32;
    float acc[2][4][4];
    #pragma unroll
    for (int mt=0;mt<2;mt++)
        #pragma unroll
        for (int nt=0;nt<4;nt++)
            #pragma unroll
            for (int u=0;u<4;u++) acc[mt][nt][u]=0.f;
    #pragma unroll
    for (int kc=0; kc<8; kc++){
        int k0 = kc*16;
        uint32_t a[2][4];
        #pragma unroll
        for (int mt=0;mt<2;mt++)
            ldsm4(a[mt], sAt + ((rb + mt*16 + (lane&15))*WS + k0 + ((lane>>4)<<3))*2);
        uint32_t b[4][4];
        #pragma unroll
        for (int pr=0;pr<2;pr++)
            ldsm4t(b[2*pr], sW + ((k0 + (lane&7) + (((lane>>3)&1)<<3))*WS
                                   + wn*32 + pr*16 + ((lane>>4)<<3))*2);
        #pragma unroll
        for (int mt=0;mt<2;mt++)
            #pragma unroll
            for (int nt=0;nt<4;nt++)
                mma16(acc[mt][nt], a[mt], &b[nt&~1][(nt&1)*2]);
    }
    #pragma unroll
    for (int mt=0;mt<2;mt++)
        #pragma unroll
        for (int nt=0;nt<4;nt++){
            int col = wn*32 + nt*8 + 2*t4;
            #pragma unroll
            for (int rp=0;rp<2;rp++){
                int row = p0 + rb + mt*16 + g + 8*rp;
                float2 o2 = { acc[mt][nt][2*rp] + bo[col],
                              acc[mt][nt][2*rp+1] + bo[col+1] };
                *(float2*)&dout[(size_t)row*DM + col] = o2;
            }
        }
}

// ---------------------------------------------------------------------------
extern "C" void kernel_launch(void* const* d_in, const int* in_sizes, int n_in,
                              void* d_out, int out_size)
{
    const float* z    = (const float*)d_in[0];
    const float* mask = (const float*)d_in[1];
    const float* ln_w = (const float*)d_in[2];
    const float* ln_b = (const float*)d_in[3];
    const float* Wq   = (const float*)d_in[4];
    const float* Wk   = (const float*)d_in[5];
    const float* Wv   = (const float*)d_in[6];
    const float* Wb   = (const float*)d_in[7];
    const float* Wg   = (const float*)d_in[8];
    const float* bg   = (const float*)d_in[9];
    const float* Wo   = (const float*)d_in[10];
    const float* bo   = (const float*)d_in[11];
    float* out = (float*)d_out;

    const int MAIN_SMEM = 193536;
    const int OUT_SMEM  = 2*128*WS*2;   // 69632
    cudaFuncSetAttribute(k_main, cudaFuncAttributeMaxDynamicSharedMemorySize, MAIN_SMEM);
    cudaFuncSetAttribute(k_out,  cudaFuncAttributeMaxDynamicSharedMemorySize, OUT_SMEM);

    k_prep<<<5, 512>>>(Wq, Wk, Wv, Wg, Wo);
    k_bias<<<NP/8, 256>>>(z, ln_w, ln_b, Wb);
    k_main<<<L, 512, MAIN_SMEM>>>(z, ln_w, ln_b, bg, mask);
    k_out <<<NP/128, 512, OUT_SMEM>>>(bo, out);
}

// round 8
// speedup vs baseline: 4.2333x; 1.0216x over previous
#include <cuda_runtime.h>
#include <cuda_fp16.h>
#include <math.h>
#include <stdint.h>

#define L   256
#define DM  128
#define NH  4
#define DK  32
#define NP  (L*L)
#define WS  136   // big-tile stride (halves)
#define AS  40    // small-tile stride (halves)

__device__ __align__(16) __half g_att[NP*DM];
__device__ __align__(16) __half g_zn[NP*DM];     // LN output, half
__device__ __align__(16) __half g_biasH[NH*NP];  // [h][i*L+j], *log2e, mask-folded
__device__ __align__(16) __half g_wT[5*128*WS];  // half W images [k][n], padded

__device__ __forceinline__ uint32_t smem_u32(const void* p){
    uint32_t a;
    asm("{ .reg .u64 t; cvta.to.shared.u64 t, %1; cvt.u32.u64 %0, t; }" : "=r"(a) : "l"(p));
    return a;
}
__device__ __forceinline__ void mma16(float* c, const uint32_t* a, const uint32_t* b){
    asm volatile("mma.sync.aligned.m16n8k16.row.col.f32.f16.f16.f32 "
        "{%0,%1,%2,%3}, {%4,%5,%6,%7}, {%8,%9}, {%0,%1,%2,%3};\n"
        : "+f"(c[0]), "+f"(c[1]), "+f"(c[2]), "+f"(c[3])
        : "r"(a[0]), "r"(a[1]), "r"(a[2]), "r"(a[3]), "r"(b[0]), "r"(b[1]));
}
__device__ __forceinline__ void ldsm4(uint32_t* r, uint32_t a){
    asm volatile("ldmatrix.sync.aligned.m8n8.x4.shared.b16 {%0,%1,%2,%3}, [%4];"
        : "=r"(r[0]), "=r"(r[1]), "=r"(r[2]), "=r"(r[3]) : "r"(a));
}
__device__ __forceinline__ void ldsm4t(uint32_t* r, uint32_t a){
    asm volatile("ldmatrix.sync.aligned.m8n8.x4.trans.shared.b16 {%0,%1,%2,%3}, [%4];"
        : "=r"(r[0]), "=r"(r[1]), "=r"(r[2]), "=r"(r[3]) : "r"(a));
}
__device__ __forceinline__ uint32_t h2u(__half2 h){ return *(uint32_t*)&h; }
__device__ __forceinline__ float ex2(float x){
    float r; asm("ex2.approx.f32 %0, %1;" : "=f"(r) : "f"(x)); return r;
}

// ---------------------------------------------------------------------------
// K0: weights -> padded half images [k=128][WS]
// ---------------------------------------------------------------------------
__global__ __launch_bounds__(512) void k_prep(const float* __restrict__ Wq,
    const float* __restrict__ Wk, const float* __restrict__ Wv,
    const float* __restrict__ Wg, const float* __restrict__ Wo)
{
    int m = blockIdx.x;
    const float* W = (m==0)?Wq:(m==1)?Wk:(m==2)?Wv:(m==3)?Wg:Wo;
    __half* dst = g_wT + m*128*WS;
    for (int e = threadIdx.x; e < 128*32; e += 512){
        int k = e>>5, c4 = e&31;
        float4 v = *(const float4*)&W[k*128 + c4*4];
        uint2 u = { h2u(__floats2half2_rn(v.x, v.y)), h2u(__floats2half2_rn(v.z, v.w)) };
        *(uint2*)&dst[k*WS + c4*4] = u;
    }
}

// ---------------------------------------------------------------------------
// K1: LN (once, store half) + bias table (half, *log2e, mask folded)
// ---------------------------------------------------------------------------
__global__ __launch_bounds__(256) void k_ln(const float* __restrict__ z,
    const float* __restrict__ ln_w, const float* __restrict__ ln_b,
    const float* __restrict__ Wb, const float* __restrict__ mask)
{
    const float LOG2E = 1.4426950408889634f;
    int w = threadIdx.x>>5, lane = threadIdx.x&31;
    int p = blockIdx.x*8 + w;
    float4 x = *(const float4*)&z[(size_t)p*DM + lane*4];
    float s = x.x+x.y+x.z+x.w;
    float sq = x.x*x.x+x.y*x.y+x.z*x.z+x.w*x.w;
    #pragma unroll
    for (int o=16;o>0;o>>=1){
        s  += __shfl_xor_sync(0xffffffffu, s,  o);
        sq += __shfl_xor_sync(0xffffffffu, sq, o);
    }
    float mu = s*(1.0f/DM);
    float var = fmaxf(sq*(1.0f/DM) - mu*mu, 0.0f);
    float rstd = rsqrtf(var + 1e-5f);
    float4 lw = *(const float4*)&ln_w[lane*4];
    float4 lb = *(const float4*)&ln_b[lane*4];
    float zn0=(x.x-mu)*rstd*lw.x+lb.x, zn1=(x.y-mu)*rstd*lw.y+lb.y;
    float zn2=(x.z-mu)*rstd*lw.z+lb.z, zn3=(x.w-mu)*rstd*lw.w+lb.w;
    uint2 u = { h2u(__floats2half2_rn(zn0,zn1)), h2u(__floats2half2_rn(zn2,zn3)) };
    *(uint2*)&g_zn[(size_t)p*DM + lane*4] = u;
    float4 w0 = *(const float4*)&Wb[(4*lane+0)*NH];
    float4 w1 = *(const float4*)&Wb[(4*lane+1)*NH];
    float4 w2 = *(const float4*)&Wb[(4*lane+2)*NH];
    float4 w3 = *(const float4*)&Wb[(4*lane+3)*NH];
    float a0 = zn0*w0.x+zn1*w1.x+zn2*w2.x+zn3*w3.x;
    float a1 = zn0*w0.y+zn1*w1.y+zn2*w2.y+zn3*w3.y;
    float a2 = zn0*w0.z+zn1*w1.z+zn2*w2.z+zn3*w3.z;
    float a3 = zn0*w0.w+zn1*w1.w+zn2*w2.w+zn3*w3.w;
    #pragma unroll
    for (int o=16;o>0;o>>=1){
        a0 += __shfl_xor_sync(0xffffffffu, a0, o);
        a1 += __shfl_xor_sync(0xffffffffu, a1, o);
        a2 += __shfl_xor_sync(0xffffffffu, a2, o);
        a3 += __shfl_xor_sync(0xffffffffu, a3, o);
    }
    if (lane==0){
        float mf = mask[p>>8]*mask[p&255];
        float ninf = -__int_as_float(0x7f800000);
        g_biasH[0*NP+p] = __float2half(mf>0.f ? a0*LOG2E : ninf);
        g_biasH[1*NP+p] = __float2half(mf>0.f ? a1*LOG2E : ninf);
        g_biasH[2*NP+p] = __float2half(mf>0.f ? a2*LOG2E : ninf);
        g_biasH[3*NP+p] = __float2half(mf>0.f ? a3*LOG2E : ninf);
    }
}

// ---------------------------------------------------------------------------
// K2: fused per (row r, head-pair): proj -> attention -> g_att
// smem: As 69632 | Qt/Kt/Vt/Gt 4x20480 | Wsl 40960  = 192512 B
// ---------------------------------------------------------------------------
__global__ __launch_bounds__(512,1) void k_main(const float* __restrict__ bg)
{
    extern __shared__ char smem[];
    __half* As = (__half*)smem;
    __half* Qt = (__half*)(smem + 69632);
    __half* Kt = Qt + 256*AS;
    __half* Vt = Kt + 256*AS;
    __half* Gt = Vt + 256*AS;
    __half* Wsl = Gt + 256*AS;
    uint32_t sAs = smem_u32(As), sQ = smem_u32(Qt), sK = smem_u32(Kt),
             sV = smem_u32(Vt), sWsl = smem_u32(Wsl);
    int r = blockIdx.x;
    int tid = threadIdx.x, w = tid>>5, lane = tid&31, g = lane>>2, t4 = lane&3;
    const float SC = 0.17677669529663687f * 1.4426950408889634f; // rscale*log2e

    // phase 0: copy zn row-tile (half) into As
    for (int e = tid; e < 4096; e += 512){
        int row = e>>4, c = e&15;
        ((uint4*)&As[row*WS])[c] = ((const uint4*)&g_zn[(size_t)(r*L+row)*DM])[c];
    }

    #pragma unroll 1
    for (int hh=0; hh<2; hh++){
        int h = blockIdx.y*2 + hh;
        __syncthreads();
        for (int e = tid; e < 2048; e += 512){   // stage head slices of 4 W
            int m = e>>9, k = (e>>2)&127, c = e&3;
            *((uint4*)&Wsl[m*128*AS + k*AS + c*8]) =
                *((const uint4*)&g_wT[m*128*WS + k*WS + h*32 + c*8]);
        }
        __syncthreads();
        // projections
        {
            int wm = w>>1, wn = w&1, rb = wm*32;
            #pragma unroll 1
            for (int mode=0; mode<4; mode++){
                uint32_t sWm = sWsl + mode*(128*AS*2);
                __half* Tt = (mode==0)?Qt:(mode==1)?Kt:(mode==2)?Vt:Gt;
                float acc[2][2][4];
                #pragma unroll
                for (int mt=0;mt<2;mt++)
                    #pragma unroll
                    for (int nt=0;nt<2;nt++)
                        #pragma unroll
                        for (int u=0;u<4;u++) acc[mt][nt][u]=0.f;
                #pragma unroll
                for (int kc=0; kc<8; kc++){
                    int k0 = kc*16;
                    uint32_t a[2][4];
                    #pragma unroll
                    for (int mt=0;mt<2;mt++)
                        ldsm4(a[mt], sAs + ((rb + mt*16 + (lane&15))*WS + k0 + ((lane>>4)<<3))*2);
                    uint32_t b[4];
                    ldsm4t(b, sWm + ((k0 + (lane&7) + (((lane>>3)&1)<<3))*AS
                                      + wn*16 + ((lane>>4)<<3))*2);
                    #pragma unroll
                    for (int mt=0;mt<2;mt++){
                        mma16(acc[mt][0], a[mt], &b[0]);
                        mma16(acc[mt][1], a[mt], &b[2]);
                    }
                }
                #pragma unroll
                for (int mt=0;mt<2;mt++)
                    #pragma unroll
                    for (int nt=0;nt<2;nt++){
                        int col = wn*16 + nt*8 + 2*t4;
                        #pragma unroll
                        for (int rp=0;rp<2;rp++){
                            int row = rb + mt*16 + g + 8*rp;
                            float v0 = acc[mt][nt][2*rp], v1 = acc[mt][nt][2*rp+1];
                            if (mode==0){ v0 *= SC; v1 *= SC; }
                            else if (mode==3){
                                v0 = 1.f/(1.f + __expf(-(v0 + bg[h*32+col])));
                                v1 = 1.f/(1.f + __expf(-(v1 + bg[h*32+col+1])));
                            }
                            *(__half2*)&Tt[row*AS + col] = __floats2half2_rn(v0, v1);
                        }
                    }
            }
        }
        __syncthreads();
        // attention: warp owns 16 query rows
        {
            int rb = w*16;
            uint32_t qa[2][4];
            #pragma unroll
            for (int kc=0;kc<2;kc++)
                ldsm4(qa[kc], sQ + ((rb + (lane&15))*AS + kc*16 + ((lane>>4)<<3))*2);
            float ssum[2] = {0.f, 0.f};
            float oacc[4][4];
            #pragma unroll
            for (int nt=0;nt<4;nt++)
                #pragma unroll
                for (int u=0;u<4;u++) oacc[nt][u]=0.f;

            #pragma unroll 1
            for (int jt=0; jt<4; jt++){
                int jb = jt*64;
                float sacc[8][4];
                #pragma unroll
                for (int nt=0;nt<8;nt++)
                    #pragma unroll
                    for (int u=0;u<4;u++) sacc[nt][u]=0.f;
                #pragma unroll
                for (int kc=0;kc<2;kc++){
                    #pragma unroll
                    for (int pr=0;pr<4;pr++){
                        uint32_t b[4];
                        ldsm4(b, sK + ((jb + pr*16 + (lane&7) + ((lane>>4)<<3))*AS
                                        + kc*16 + (((lane>>3)&1)<<3))*2);
                        mma16(sacc[2*pr],   qa[kc], &b[0]);
                        mma16(sacc[2*pr+1], qa[kc], &b[2]);
                    }
                }
                uint32_t ph[8][2];
                float psum[2] = {0.f, 0.f};
                #pragma unroll
                for (int nt=0;nt<8;nt++){
                    int j0 = jb + nt*8 + 2*t4;
                    #pragma unroll
                    for (int rp=0;rp<2;rp++){
                        int i = rb + g + 8*rp;
                        float2 bi = __half22float2(*(const __half2*)&g_biasH[h*NP + i*L + j0]);
                        float p0 = ex2(sacc[nt][2*rp]   + bi.x);
                        float p1 = ex2(sacc[nt][2*rp+1] + bi.y);
                        psum[rp] += p0 + p1;
                        ph[nt][rp] = h2u(__floats2half2_rn(p0, p1));
                    }
                }
                #pragma unroll
                for (int rp=0;rp<2;rp++){
                    float s = psum[rp];
                    s += __shfl_xor_sync(0xffffffffu, s, 1);
                    s += __shfl_xor_sync(0xffffffffu, s, 2);
                    ssum[rp] += s;
                }
                #pragma unroll
                for (int kc2=0;kc2<4;kc2++){
                    uint32_t pa[4] = { ph[2*kc2][0], ph[2*kc2][1], ph[2*kc2+1][0], ph[2*kc2+1][1] };
                    #pragma unroll
                    for (int pr=0;pr<2;pr++){
                        uint32_t b[4];
                        ldsm4t(b, sV + ((jb + kc2*16 + (lane&7) + (((lane>>3)&1)<<3))*AS
                                         + pr*16 + ((lane>>4)<<3))*2);
                        mma16(oacc[2*pr],   pa, &b[0]);
                        mma16(oacc[2*pr+1], pa, &b[2]);
                    }
                }
            }
            float rinv[2] = { 1.f/ssum[0], 1.f/ssum[1] };
            #pragma unroll
            for (int nt=0;nt<4;nt++)
                #pragma unroll
                for (int rp=0;rp<2;rp++){
                    int i = rb + g + 8*rp;
                    int d = nt*8 + 2*t4;
                    float2 gf = __half22float2(*(__half2*)&Gt[i*AS + d]);
                    *(__half2*)&g_att[(size_t)(r*L+i)*DM + h*DK + d] = __floats2half2_rn(
                        oacc[nt][2*rp]  *rinv[rp]*gf.x,
                        oacc[nt][2*rp+1]*rinv[rp]*gf.y);
                }
        }
    }
}

// ---------------------------------------------------------------------------
// K3: out = g_att @ Wo + bo
// ---------------------------------------------------------------------------
__global__ __launch_bounds__(512,1) void k_out(const float* __restrict__ bo,
                                               float* __restrict__ dout)
{
    extern __shared__ char smem[];
    __half* At = (__half*)smem;
    __half* Ws = (__half*)(smem + 128*WS*2);
    uint32_t sAt = smem_u32(At), sW = smem_u32(Ws);
    int tid = threadIdx.x, w = tid>>5, lane = tid&31, g = lane>>2, t4 = lane&3;
    int wm = w>>2, wn = w&3;
    int p0 = blockIdx.x*128;

    for (int e = tid; e < 2048; e += 512){
        int row = e>>4, c = e&15;
        ((uint4*)At)[row*17 + c] = ((const uint4*)g_att)[(size_t)(p0+row)*16 + c];
    }
    for (int e = tid; e < 128*WS/8; e += 512)
        ((uint4*)Ws)[e] = ((const uint4*)(g_wT + 4*128*WS))[e];
    __syncthreads();

    int rb = wm*32;
    float acc[2][4][4];
    #pragma unroll
    for (int mt=0;mt<2;mt++)
        #pragma unroll
        for (int nt=0;nt<4;nt++)
            #pragma unroll
            for (int u=0;u<4;u++) acc[mt][nt][u]=0.f;
    #pragma unroll
    for (int kc=0; kc<8; kc++){
        int k0 = kc*16;
        uint32_t a[2][4];
        #pragma unroll
        for (int mt=0;mt<2;mt++)
            ldsm4(a[mt], sAt + ((rb + mt*16 + (lane&15))*WS + k0 + ((lane>>4)<<3))*2);
        uint32_t b[4][4];
        #pragma unroll
        for (int pr=0;pr<2;pr++)
            ldsm4t(b[2*pr], sW + ((k0 + (lane&7) + (((lane>>3)&1)<<3))*WS
                                   + wn*32 + pr*16 + ((lane>>4)<<3))*2);
        #pragma unroll
        for (int mt=0;mt<2;mt++)
            #pragma unroll
            for (int nt=0;nt<4;nt++)
                mma16(acc[mt][nt], a[mt], &b[nt&~1][(nt&1)*2]);
    }
    #pragma unroll
    for (int mt=0;mt<2;mt++)
        #pragma unroll
        for (int nt=0;nt<4;nt++){
            int col = wn*32 + nt*8 + 2*t4;
            #pragma unroll
            for (int rp=0;rp<2;rp++){
                int row = p0 + rb + mt*16 + g + 8*rp;
                float2 o2 = { acc[mt][nt][2*rp] + bo[col],
                              acc[mt][nt][2*rp+1] + bo[col+1] };
                *(float2*)&dout[(size_t)row*DM + col] = o2;
            }
        }
}

// ---------------------------------------------------------------------------
extern "C" void kernel_launch(void* const* d_in, const int* in_sizes, int n_in,
                              void* d_out, int out_size)
{
    const float* z    = (const float*)d_in[0];
    const float* mask = (const float*)d_in[1];
    const float* ln_w = (const float*)d_in[2];
    const float* ln_b = (const float*)d_in[3];
    const float* Wq   = (const float*)d_in[4];
    const float* Wk   = (const float*)d_in[5];
    const float* Wv   = (const float*)d_in[6];
    const float* Wb   = (const float*)d_in[7];
    const float* Wg   = (const float*)d_in[8];
    const float* bg   = (const float*)d_in[9];
    const float* Wo   = (const float*)d_in[10];
    const float* bo   = (const float*)d_in[11];
    float* out = (float*)d_out;

    const int MAIN_SMEM = 192512;
    const int OUT_SMEM  = 2*128*WS*2;
    cudaFuncSetAttribute(k_main, cudaFuncAttributeMaxDynamicSharedMemorySize, MAIN_SMEM);
    cudaFuncSetAttribute(k_out,  cudaFuncAttributeMaxDynamicSharedMemorySize, OUT_SMEM);

    k_prep<<<5, 512>>>(Wq, Wk, Wv, Wg, Wo);
    k_ln  <<<NP/8, 256>>>(z, ln_w, ln_b, Wb, mask);
    k_main<<<dim3(L,2), 512, MAIN_SMEM>>>(bg);
    k_out <<<NP/128, 512, OUT_SMEM>>>(bo, out);
}

// round 9
// speedup vs baseline: 4.5423x; 1.0730x over previous
#include <cuda_runtime.h>
#include <cuda_fp16.h>
#include <math.h>
#include <stdint.h>

#define L   256
#define DM  128
#define NH  4
#define DK  32
#define NP  (L*L)
#define WS  136   // big-tile stride (halves)
#define AS  40    // small-tile stride (halves)

__device__ __align__(16) __half g_att[NP*DM];
__device__ __align__(16) __half g_zn[NP*DM];     // LN output, half
__device__ __align__(16) __half g_biasH[NH*NP];  // [h][i*L+j], *log2e, mask-folded
__device__ __align__(16) __half g_wT[5*128*WS];  // half W images [k][n], padded

__device__ __forceinline__ uint32_t smem_u32(const void* p){
    uint32_t a;
    asm("{ .reg .u64 t; cvta.to.shared.u64 t, %1; cvt.u32.u64 %0, t; }" : "=r"(a) : "l"(p));
    return a;
}
__device__ __forceinline__ void mma16(float* c, const uint32_t* a, const uint32_t* b){
    asm volatile("mma.sync.aligned.m16n8k16.row.col.f32.f16.f16.f32 "
        "{%0,%1,%2,%3}, {%4,%5,%6,%7}, {%8,%9}, {%0,%1,%2,%3};\n"
        : "+f"(c[0]), "+f"(c[1]), "+f"(c[2]), "+f"(c[3])
        : "r"(a[0]), "r"(a[1]), "r"(a[2]), "r"(a[3]), "r"(b[0]), "r"(b[1]));
}
__device__ __forceinline__ void ldsm4(uint32_t* r, uint32_t a){
    asm volatile("ldmatrix.sync.aligned.m8n8.x4.shared.b16 {%0,%1,%2,%3}, [%4];"
        : "=r"(r[0]), "=r"(r[1]), "=r"(r[2]), "=r"(r[3]) : "r"(a));
}
__device__ __forceinline__ void ldsm4t(uint32_t* r, uint32_t a){
    asm volatile("ldmatrix.sync.aligned.m8n8.x4.trans.shared.b16 {%0,%1,%2,%3}, [%4];"
        : "=r"(r[0]), "=r"(r[1]), "=r"(r[2]), "=r"(r[3]) : "r"(a));
}
__device__ __forceinline__ uint32_t h2u(__half2 h){ return *(uint32_t*)&h; }
__device__ __forceinline__ float ex2(float x){
    float r; asm("ex2.approx.f32 %0, %1;" : "=f"(r) : "f"(x)); return r;
}

// ---------------------------------------------------------------------------
// K1: blocks 0..4: weights -> padded half images; blocks 5+: LN + bias table
// ---------------------------------------------------------------------------
__global__ __launch_bounds__(512) void k_ln(const float* __restrict__ z,
    const float* __restrict__ ln_w, const float* __restrict__ ln_b,
    const float* __restrict__ Wb, const float* __restrict__ mask,
    const float* __restrict__ Wq, const float* __restrict__ Wk,
    const float* __restrict__ Wv, const float* __restrict__ Wg,
    const float* __restrict__ Wo)
{
    if (blockIdx.x < 5){
        int m = blockIdx.x;
        const float* W = (m==0)?Wq:(m==1)?Wk:(m==2)?Wv:(m==3)?Wg:Wo;
        __half* dst = g_wT + m*128*WS;
        for (int e = threadIdx.x; e < 128*32; e += 512){
            int k = e>>5, c4 = e&31;
            float4 v = *(const float4*)&W[k*128 + c4*4];
            uint2 u = { h2u(__floats2half2_rn(v.x, v.y)), h2u(__floats2half2_rn(v.z, v.w)) };
            *(uint2*)&dst[k*WS + c4*4] = u;
        }
        return;
    }
    const float LOG2E = 1.4426950408889634f;
    int w = threadIdx.x>>5, lane = threadIdx.x&31;
    int p = (blockIdx.x-5)*16 + w;
    float4 x = *(const float4*)&z[(size_t)p*DM + lane*4];
    float s = x.x+x.y+x.z+x.w;
    float sq = x.x*x.x+x.y*x.y+x.z*x.z+x.w*x.w;
    #pragma unroll
    for (int o=16;o>0;o>>=1){
        s  += __shfl_xor_sync(0xffffffffu, s,  o);
        sq += __shfl_xor_sync(0xffffffffu, sq, o);
    }
    float mu = s*(1.0f/DM);
    float var = fmaxf(sq*(1.0f/DM) - mu*mu, 0.0f);
    float rstd = rsqrtf(var + 1e-5f);
    float4 lw = *(const float4*)&ln_w[lane*4];
    float4 lb = *(const float4*)&ln_b[lane*4];
    float zn0=(x.x-mu)*rstd*lw.x+lb.x, zn1=(x.y-mu)*rstd*lw.y+lb.y;
    float zn2=(x.z-mu)*rstd*lw.z+lb.z, zn3=(x.w-mu)*rstd*lw.w+lb.w;
    uint2 u = { h2u(__floats2half2_rn(zn0,zn1)), h2u(__floats2half2_rn(zn2,zn3)) };
    *(uint2*)&g_zn[(size_t)p*DM + lane*4] = u;
    float4 w0 = *(const float4*)&Wb[(4*lane+0)*NH];
    float4 w1 = *(const float4*)&Wb[(4*lane+1)*NH];
    float4 w2 = *(const float4*)&Wb[(4*lane+2)*NH];
    float4 w3 = *(const float4*)&Wb[(4*lane+3)*NH];
    float a0 = zn0*w0.x+zn1*w1.x+zn2*w2.x+zn3*w3.x;
    float a1 = zn0*w0.y+zn1*w1.y+zn2*w2.y+zn3*w3.y;
    float a2 = zn0*w0.z+zn1*w1.z+zn2*w2.z+zn3*w3.z;
    float a3 = zn0*w0.w+zn1*w1.w+zn2*w2.w+zn3*w3.w;
    #pragma unroll
    for (int o=16;o>0;o>>=1){
        a0 += __shfl_xor_sync(0xffffffffu, a0, o);
        a1 += __shfl_xor_sync(0xffffffffu, a1, o);
        a2 += __shfl_xor_sync(0xffffffffu, a2, o);
        a3 += __shfl_xor_sync(0xffffffffu, a3, o);
    }
    if (lane==0){
        float mf = mask[p>>8]*mask[p&255];
        float ninf = -__int_as_float(0x7f800000);
        g_biasH[0*NP+p] = __float2half(mf>0.f ? a0*LOG2E : ninf);
        g_biasH[1*NP+p] = __float2half(mf>0.f ? a1*LOG2E : ninf);
        g_biasH[2*NP+p] = __float2half(mf>0.f ? a2*LOG2E : ninf);
        g_biasH[3*NP+p] = __float2half(mf>0.f ? a3*LOG2E : ninf);
    }
}

// ---------------------------------------------------------------------------
// K2: fused per (row r, head h): proj -> attention -> g_att. grid (L, NH).
// smem: As 69632 | Qt/Kt/Vt/Gt 4x20480 | Wsl 40960  = 192512 B
// ---------------------------------------------------------------------------
__global__ __launch_bounds__(512,1) void k_main(const float* __restrict__ bg)
{
    extern __shared__ char smem[];
    __half* As = (__half*)smem;
    __half* Qt = (__half*)(smem + 69632);
    __half* Kt = Qt + 256*AS;
    __half* Vt = Kt + 256*AS;
    __half* Gt = Vt + 256*AS;
    __half* Wsl = Gt + 256*AS;
    uint32_t sAs = smem_u32(As), sQ = smem_u32(Qt), sK = smem_u32(Kt),
             sV = smem_u32(Vt), sWsl = smem_u32(Wsl);
    int r = blockIdx.x, h = blockIdx.y;
    int tid = threadIdx.x, w = tid>>5, lane = tid&31, g = lane>>2, t4 = lane&3;
    const float SC = 0.17677669529663687f * 1.4426950408889634f; // rscale*log2e

    // stage zn row-tile and W head-slices (no dependency between them)
    for (int e = tid; e < 4096; e += 512){
        int row = e>>4, c = e&15;
        ((uint4*)&As[row*WS])[c] = ((const uint4*)&g_zn[(size_t)(r*L+row)*DM])[c];
    }
    for (int e = tid; e < 2048; e += 512){
        int m = e>>9, k = (e>>2)&127, c = e&3;
        *((uint4*)&Wsl[m*128*AS + k*AS + c*8]) =
            *((const uint4*)&g_wT[m*128*WS + k*WS + h*32 + c*8]);
    }
    __syncthreads();
    // projections: warp wm=w>>1 rows, wn=w&1 16-col half
    {
        int wm = w>>1, wn = w&1, rb = wm*32;
        #pragma unroll 1
        for (int mode=0; mode<4; mode++){
            uint32_t sWm = sWsl + mode*(128*AS*2);
            __half* Tt = (mode==0)?Qt:(mode==1)?Kt:(mode==2)?Vt:Gt;
            float acc[2][2][4];
            #pragma unroll
            for (int mt=0;mt<2;mt++)
                #pragma unroll
                for (int nt=0;nt<2;nt++)
                    #pragma unroll
                    for (int u=0;u<4;u++) acc[mt][nt][u]=0.f;
            #pragma unroll
            for (int kc=0; kc<8; kc++){
                int k0 = kc*16;
                uint32_t a[2][4];
                #pragma unroll
                for (int mt=0;mt<2;mt++)
                    ldsm4(a[mt], sAs + ((rb + mt*16 + (lane&15))*WS + k0 + ((lane>>4)<<3))*2);
                uint32_t b[4];
                ldsm4t(b, sWm + ((k0 + (lane&7) + (((lane>>3)&1)<<3))*AS
                                  + wn*16 + ((lane>>4)<<3))*2);
                #pragma unroll
                for (int mt=0;mt<2;mt++){
                    mma16(acc[mt][0], a[mt], &b[0]);
                    mma16(acc[mt][1], a[mt], &b[2]);
                }
            }
            #pragma unroll
            for (int mt=0;mt<2;mt++)
                #pragma unroll
                for (int nt=0;nt<2;nt++){
                    int col = wn*16 + nt*8 + 2*t4;
                    #pragma unroll
                    for (int rp=0;rp<2;rp++){
                        int row = rb + mt*16 + g + 8*rp;
                        float v0 = acc[mt][nt][2*rp], v1 = acc[mt][nt][2*rp+1];
                        if (mode==0){ v0 *= SC; v1 *= SC; }
                        else if (mode==3){
                            v0 = 1.f/(1.f + __expf(-(v0 + bg[h*32+col])));
                            v1 = 1.f/(1.f + __expf(-(v1 + bg[h*32+col+1])));
                        }
                        *(__half2*)&Tt[row*AS + col] = __floats2half2_rn(v0, v1);
                    }
                }
        }
    }
    __syncthreads();
    // attention: warp owns 16 query rows
    {
        int rb = w*16;
        uint32_t qa[2][4];
        #pragma unroll
        for (int kc=0;kc<2;kc++)
            ldsm4(qa[kc], sQ + ((rb + (lane&15))*AS + kc*16 + ((lane>>4)<<3))*2);
        float ssum[2] = {0.f, 0.f};
        float oacc[4][4];
        #pragma unroll
        for (int nt=0;nt<4;nt++)
            #pragma unroll
            for (int u=0;u<4;u++) oacc[nt][u]=0.f;

        #pragma unroll 1
        for (int jt=0; jt<4; jt++){
            int jb = jt*64;
            float sacc[8][4];
            #pragma unroll
            for (int nt=0;nt<8;nt++)
                #pragma unroll
                for (int u=0;u<4;u++) sacc[nt][u]=0.f;
            #pragma unroll
            for (int kc=0;kc<2;kc++){
                #pragma unroll
                for (int pr=0;pr<4;pr++){
                    uint32_t b[4];
                    ldsm4(b, sK + ((jb + pr*16 + (lane&7) + ((lane>>4)<<3))*AS
                                    + kc*16 + (((lane>>3)&1)<<3))*2);
                    mma16(sacc[2*pr],   qa[kc], &b[0]);
                    mma16(sacc[2*pr+1], qa[kc], &b[2]);
                }
            }
            uint32_t ph[8][2];
            float psum[2] = {0.f, 0.f};
            #pragma unroll
            for (int nt=0;nt<8;nt++){
                int j0 = jb + nt*8 + 2*t4;
                #pragma unroll
                for (int rp=0;rp<2;rp++){
                    int i = rb + g + 8*rp;
                    float2 bi = __half22float2(*(const __half2*)&g_biasH[h*NP + i*L + j0]);
                    float p0 = ex2(sacc[nt][2*rp]   + bi.x);
                    float p1 = ex2(sacc[nt][2*rp+1] + bi.y);
                    psum[rp] += p0 + p1;
                    ph[nt][rp] = h2u(__floats2half2_rn(p0, p1));
                }
            }
            #pragma unroll
            for (int rp=0;rp<2;rp++){
                float s = psum[rp];
                s += __shfl_xor_sync(0xffffffffu, s, 1);
                s += __shfl_xor_sync(0xffffffffu, s, 2);
                ssum[rp] += s;
            }
            #pragma unroll
            for (int kc2=0;kc2<4;kc2++){
                uint32_t pa[4] = { ph[2*kc2][0], ph[2*kc2][1], ph[2*kc2+1][0], ph[2*kc2+1][1] };
                #pragma unroll
                for (int pr=0;pr<2;pr++){
                    uint32_t b[4];
                    ldsm4t(b, sV + ((jb + kc2*16 + (lane&7) + (((lane>>3)&1)<<3))*AS
                                     + pr*16 + ((lane>>4)<<3))*2);
                    mma16(oacc[2*pr],   pa, &b[0]);
                    mma16(oacc[2*pr+1], pa, &b[2]);
                }
            }
        }
        float rinv[2] = { 1.f/ssum[0], 1.f/ssum[1] };
        #pragma unroll
        for (int nt=0;nt<4;nt++)
            #pragma unroll
            for (int rp=0;rp<2;rp++){
                int i = rb + g + 8*rp;
                int d = nt*8 + 2*t4;
                float2 gf = __half22float2(*(__half2*)&Gt[i*AS + d]);
                *(__half2*)&g_att[(size_t)(r*L+i)*DM + h*DK + d] = __floats2half2_rn(
                    oacc[nt][2*rp]  *rinv[rp]*gf.x,
                    oacc[nt][2*rp+1]*rinv[rp]*gf.y);
            }
    }
}

// ---------------------------------------------------------------------------
// K3: out = g_att @ Wo + bo. 256 thr, 64 rows/block -> 2 CTAs/SM.
// ---------------------------------------------------------------------------
__global__ __launch_bounds__(256,2) void k_out(const float* __restrict__ bo,
                                               float* __restrict__ dout)
{
    extern __shared__ char smem[];
    __half* At = (__half*)smem;                  // 64 x WS
    __half* Ws = (__half*)(smem + 64*WS*2);      // 128 x WS
    uint32_t sAt = smem_u32(At), sW = smem_u32(Ws);
    int tid = threadIdx.x, w = tid>>5, lane = tid&31, g = lane>>2, t4 = lane&3;
    int wm = w>>2, wn = w&3;
    int p0 = blockIdx.x*64;

    for (int e = tid; e < 1024; e += 256){
        int row = e>>4, c = e&15;
        ((uint4*)At)[row*17 + c] = ((const uint4*)g_att)[(size_t)(p0+row)*16 + c];
    }
    for (int e = tid; e < 128*WS/8; e += 256)
        ((uint4*)Ws)[e] = ((const uint4*)(g_wT + 4*128*WS))[e];
    __syncthreads();

    int rb = wm*32;
    float acc[2][4][4];
    #pragma unroll
    for (int mt=0;mt<2;mt++)
        #pragma unroll
        for (int nt=0;nt<4;nt++)
            #pragma unroll
            for (int u=0;u<4;u++) acc[mt][nt][u]=0.f;
    #pragma unroll
    for (int kc=0; kc<8; kc++){
        int k0 = kc*16;
        uint32_t a[2][4];
        #pragma unroll
        for (int mt=0;mt<2;mt++)
            ldsm4(a[mt], sAt + ((rb + mt*16 + (lane&15))*WS + k0 + ((lane>>4)<<3))*2);
        uint32_t b[4][4];
        #pragma unroll
        for (int pr=0;pr<2;pr++)
            ldsm4t(b[2*pr], sW + ((k0 + (lane&7) + (((lane>>3)&1)<<3))*WS
                                   + wn*32 + pr*16 + ((lane>>4)<<3))*2);
        #pragma unroll
        for (int mt=0;mt<2;mt++)
            #pragma unroll
            for (int nt=0;nt<4;nt++)
                mma16(acc[mt][nt], a[mt], &b[nt&~1][(nt&1)*2]);
    }
    #pragma unroll
    for (int mt=0;mt<2;mt++)
        #pragma unroll
        for (int nt=0;nt<4;nt++){
            int col = wn*32 + nt*8 + 2*t4;
            #pragma unroll
            for (int rp=0;rp<2;rp++){
                int row = p0 + rb + mt*16 + g + 8*rp;
                float2 o2 = { acc[mt][nt][2*rp] + bo[col],
                              acc[mt][nt][2*rp+1] + bo[col+1] };
                *(float2*)&dout[(size_t)row*DM + col] = o2;
            }
        }
}

// ---------------------------------------------------------------------------
extern "C" void kernel_launch(void* const* d_in, const int* in_sizes, int n_in,
                              void* d_out, int out_size)
{
    const float* z    = (const float*)d_in[0];
    const float* mask = (const float*)d_in[1];
    const float* ln_w = (const float*)d_in[2];
    const float* ln_b = (const float*)d_in[3];
    const float* Wq   = (const float*)d_in[4];
    const float* Wk   = (const float*)d_in[5];
    const float* Wv   = (const float*)d_in[6];
    const float* Wb   = (const float*)d_in[7];
    const float* Wg   = (const float*)d_in[8];
    const float* bg   = (const float*)d_in[9];
    const float* Wo   = (const float*)d_in[10];
    const float* bo   = (const float*)d_in[11];
    float* out = (float*)d_out;

    const int MAIN_SMEM = 192512;
    const int OUT_SMEM  = 64*WS*2 + 128*WS*2;   // 52224
    cudaFuncSetAttribute(k_main, cudaFuncAttributeMaxDynamicSharedMemorySize, MAIN_SMEM);
    cudaFuncSetAttribute(k_out,  cudaFuncAttributeMaxDynamicSharedMemorySize, OUT_SMEM);

    k_ln  <<<5 + NP/16, 512>>>(z, ln_w, ln_b, Wb, mask, Wq, Wk, Wv, Wg, Wo);
    k_main<<<dim3(L,NH), 512, MAIN_SMEM>>>(bg);
    k_out <<<NP/64, 256, OUT_SMEM>>>(bo, out);
}

// round 10
// speedup vs baseline: 4.7749x; 1.0512x over previous
#include <cuda_runtime.h>
#include <cuda_fp16.h>
#include <math.h>
#include <stdint.h>

#define L   256
#define DM  128
#define NH  4
#define DK  32
#define NP  (L*L)
#define WS  136   // big-tile stride (halves)
#define AS  40    // small-tile stride (halves)

__device__ __align__(16) __half g_att[NP*DM];
__device__ __align__(16) __half g_zn[NP*DM];     // LN output, half
__device__ __align__(16) __half g_biasH[NH*NP];  // [h][i*L+j], *log2e, mask-folded
__device__ __align__(16) __half g_wT[5*128*WS];  // half W images [k][n], padded

__device__ __forceinline__ uint32_t smem_u32(const void* p){
    uint32_t a;
    asm("{ .reg .u64 t; cvta.to.shared.u64 t, %1; cvt.u32.u64 %0, t; }" : "=r"(a) : "l"(p));
    return a;
}
__device__ __forceinline__ void mma16(float* c, const uint32_t* a, const uint32_t* b){
    asm volatile("mma.sync.aligned.m16n8k16.row.col.f32.f16.f16.f32 "
        "{%0,%1,%2,%3}, {%4,%5,%6,%7}, {%8,%9}, {%0,%1,%2,%3};\n"
        : "+f"(c[0]), "+f"(c[1]), "+f"(c[2]), "+f"(c[3])
        : "r"(a[0]), "r"(a[1]), "r"(a[2]), "r"(a[3]), "r"(b[0]), "r"(b[1]));
}
__device__ __forceinline__ void ldsm4(uint32_t* r, uint32_t a){
    asm volatile("ldmatrix.sync.aligned.m8n8.x4.shared.b16 {%0,%1,%2,%3}, [%4];"
        : "=r"(r[0]), "=r"(r[1]), "=r"(r[2]), "=r"(r[3]) : "r"(a));
}
__device__ __forceinline__ void ldsm4t(uint32_t* r, uint32_t a){
    asm volatile("ldmatrix.sync.aligned.m8n8.x4.trans.shared.b16 {%0,%1,%2,%3}, [%4];"
        : "=r"(r[0]), "=r"(r[1]), "=r"(r[2]), "=r"(r[3]) : "r"(a));
}
__device__ __forceinline__ void ldsm2t(uint32_t* r, uint32_t a){
    asm volatile("ldmatrix.sync.aligned.m8n8.x2.trans.shared.b16 {%0,%1}, [%2];"
        : "=r"(r[0]), "=r"(r[1]) : "r"(a));
}
__device__ __forceinline__ uint32_t h2u(__half2 h){ return *(uint32_t*)&h; }
__device__ __forceinline__ float ex2(float x){
    float r; asm("ex2.approx.f32 %0, %1;" : "=f"(r) : "f"(x)); return r;
}

// ---------------------------------------------------------------------------
// K1: blocks 0..4: weight images; blocks 5+: LN + bias (4 positions per warp)
// ---------------------------------------------------------------------------
__global__ __launch_bounds__(512) void k_ln(const float* __restrict__ z,
    const float* __restrict__ ln_w, const float* __restrict__ ln_b,
    const float* __restrict__ Wb, const float* __restrict__ mask,
    const float* __restrict__ Wq, const float* __restrict__ Wk,
    const float* __restrict__ Wv, const float* __restrict__ Wg,
    const float* __restrict__ Wo)
{
    if (blockIdx.x < 5){
        int m = blockIdx.x;
        const float* W = (m==0)?Wq:(m==1)?Wk:(m==2)?Wv:(m==3)?Wg:Wo;
        __half* dst = g_wT + m*128*WS;
        for (int e = threadIdx.x; e < 128*32; e += 512){
            int k = e>>5, c4 = e&31;
            float4 v = *(const float4*)&W[k*128 + c4*4];
            uint2 u = { h2u(__floats2half2_rn(v.x, v.y)), h2u(__floats2half2_rn(v.z, v.w)) };
            *(uint2*)&dst[k*WS + c4*4] = u;
        }
        return;
    }
    const float LOG2E = 1.4426950408889634f;
    int w = threadIdx.x>>5, lane = threadIdx.x&31;
    int pbase = (blockIdx.x-5)*64 + w*4;
    float4 lw = *(const float4*)&ln_w[lane*4];
    float4 lb = *(const float4*)&ln_b[lane*4];
    float4 w0 = *(const float4*)&Wb[(4*lane+0)*NH];
    float4 w1 = *(const float4*)&Wb[(4*lane+1)*NH];
    float4 w2 = *(const float4*)&Wb[(4*lane+2)*NH];
    float4 w3 = *(const float4*)&Wb[(4*lane+3)*NH];
    #pragma unroll
    for (int pp=0; pp<4; pp++){
        int p = pbase + pp;
        float4 x = *(const float4*)&z[(size_t)p*DM + lane*4];
        float s = x.x+x.y+x.z+x.w;
        float sq = x.x*x.x+x.y*x.y+x.z*x.z+x.w*x.w;
        #pragma unroll
        for (int o=16;o>0;o>>=1){
            s  += __shfl_xor_sync(0xffffffffu, s,  o);
            sq += __shfl_xor_sync(0xffffffffu, sq, o);
        }
        float mu = s*(1.0f/DM);
        float var = fmaxf(sq*(1.0f/DM) - mu*mu, 0.0f);
        float rstd = rsqrtf(var + 1e-5f);
        float zn0=(x.x-mu)*rstd*lw.x+lb.x, zn1=(x.y-mu)*rstd*lw.y+lb.y;
        float zn2=(x.z-mu)*rstd*lw.z+lb.z, zn3=(x.w-mu)*rstd*lw.w+lb.w;
        uint2 u = { h2u(__floats2half2_rn(zn0,zn1)), h2u(__floats2half2_rn(zn2,zn3)) };
        *(uint2*)&g_zn[(size_t)p*DM + lane*4] = u;
        float a0 = zn0*w0.x+zn1*w1.x+zn2*w2.x+zn3*w3.x;
        float a1 = zn0*w0.y+zn1*w1.y+zn2*w2.y+zn3*w3.y;
        float a2 = zn0*w0.z+zn1*w1.z+zn2*w2.z+zn3*w3.z;
        float a3 = zn0*w0.w+zn1*w1.w+zn2*w2.w+zn3*w3.w;
        #pragma unroll
        for (int o=16;o>0;o>>=1){
            a0 += __shfl_xor_sync(0xffffffffu, a0, o);
            a1 += __shfl_xor_sync(0xffffffffu, a1, o);
            a2 += __shfl_xor_sync(0xffffffffu, a2, o);
            a3 += __shfl_xor_sync(0xffffffffu, a3, o);
        }
        if (lane==0){
            float mf = mask[p>>8]*mask[p&255];
            float ninf = -__int_as_float(0x7f800000);
            g_biasH[0*NP+p] = __float2half(mf>0.f ? a0*LOG2E : ninf);
            g_biasH[1*NP+p] = __float2half(mf>0.f ? a1*LOG2E : ninf);
            g_biasH[2*NP+p] = __float2half(mf>0.f ? a2*LOG2E : ninf);
            g_biasH[3*NP+p] = __float2half(mf>0.f ? a3*LOG2E : ninf);
        }
    }
}

// ---------------------------------------------------------------------------
// K2: fused per (row r, head h): proj -> attention -> g_att. grid (L, NH).
// smem: As 69632 | Qt/Kt/Vt/Gt 4x20480 | Wsl 40960  = 192512 B
// ---------------------------------------------------------------------------
__global__ __launch_bounds__(512,1) void k_main(const float* __restrict__ bg)
{
    extern __shared__ char smem[];
    __half* As = (__half*)smem;
    __half* Qt = (__half*)(smem + 69632);
    __half* Kt = Qt + 256*AS;
    __half* Vt = Kt + 256*AS;
    __half* Gt = Vt + 256*AS;
    __half* Wsl = Gt + 256*AS;
    uint32_t sAs = smem_u32(As), sQ = smem_u32(Qt), sK = smem_u32(Kt),
             sV = smem_u32(Vt), sWsl = smem_u32(Wsl);
    int r = blockIdx.x, h = blockIdx.y;
    int tid = threadIdx.x, w = tid>>5, lane = tid&31, g = lane>>2, t4 = lane&3;
    const float SC = 0.17677669529663687f * 1.4426950408889634f; // rscale*log2e

    // stage zn row-tile, W head-slices, and ones-column of Vt (cols 32..39)
    for (int e = tid; e < 4096; e += 512){
        int row = e>>4, c = e&15;
        ((uint4*)&As[row*WS])[c] = ((const uint4*)&g_zn[(size_t)(r*L+row)*DM])[c];
    }
    for (int e = tid; e < 2048; e += 512){
        int m = e>>9, k = (e>>2)&127, c = e&3;
        *((uint4*)&Wsl[m*128*AS + k*AS + c*8]) =
            *((const uint4*)&g_wT[m*128*WS + k*WS + h*32 + c*8]);
    }
    if (tid < 256){
        uint4 ones = { 0x00003C00u, 0u, 0u, 0u };  // halves: 1.0, 0 x7
        *(uint4*)&Vt[tid*AS + 32] = ones;
    }
    __syncthreads();
    // projections: warp wm=w>>1 rows, wn=w&1 16-col half
    {
        int wm = w>>1, wn = w&1, rb = wm*32;
        #pragma unroll 1
        for (int mode=0; mode<4; mode++){
            uint32_t sWm = sWsl + mode*(128*AS*2);
            __half* Tt = (mode==0)?Qt:(mode==1)?Kt:(mode==2)?Vt:Gt;
            float acc[2][2][4];
            #pragma unroll
            for (int mt=0;mt<2;mt++)
                #pragma unroll
                for (int nt=0;nt<2;nt++)
                    #pragma unroll
                    for (int u=0;u<4;u++) acc[mt][nt][u]=0.f;
            #pragma unroll
            for (int kc=0; kc<8; kc++){
                int k0 = kc*16;
                uint32_t a[2][4];
                #pragma unroll
                for (int mt=0;mt<2;mt++)
                    ldsm4(a[mt], sAs + ((rb + mt*16 + (lane&15))*WS + k0 + ((lane>>4)<<3))*2);
                uint32_t b[4];
                ldsm4t(b, sWm + ((k0 + (lane&7) + (((lane>>3)&1)<<3))*AS
                                  + wn*16 + ((lane>>4)<<3))*2);
                #pragma unroll
                for (int mt=0;mt<2;mt++){
                    mma16(acc[mt][0], a[mt], &b[0]);
                    mma16(acc[mt][1], a[mt], &b[2]);
                }
            }
            #pragma unroll
            for (int mt=0;mt<2;mt++)
                #pragma unroll
                for (int nt=0;nt<2;nt++){
                    int col = wn*16 + nt*8 + 2*t4;
                    #pragma unroll
                    for (int rp=0;rp<2;rp++){
                        int row = rb + mt*16 + g + 8*rp;
                        float v0 = acc[mt][nt][2*rp], v1 = acc[mt][nt][2*rp+1];
                        if (mode==0){ v0 *= SC; v1 *= SC; }
                        else if (mode==3){
                            v0 = 1.f/(1.f + __expf(-(v0 + bg[h*32+col])));
                            v1 = 1.f/(1.f + __expf(-(v1 + bg[h*32+col+1])));
                        }
                        *(__half2*)&Tt[row*AS + col] = __floats2half2_rn(v0, v1);
                    }
                }
        }
    }
    __syncthreads();
    // attention: warp owns 16 query rows
    {
        int rb = w*16;
        uint32_t qa[2][4];
        #pragma unroll
        for (int kc=0;kc<2;kc++)
            ldsm4(qa[kc], sQ + ((rb + (lane&15))*AS + kc*16 + ((lane>>4)<<3))*2);
        float oacc[4][4];
        float oaccS[4];
        #pragma unroll
        for (int nt=0;nt<4;nt++)
            #pragma unroll
            for (int u=0;u<4;u++) oacc[nt][u]=0.f;
        #pragma unroll
        for (int u=0;u<4;u++) oaccS[u]=0.f;

        #pragma unroll 1
        for (int jt=0; jt<4; jt++){
            int jb = jt*64;
            // bias prefetch: issue LDGs before the mma chain
            uint32_t breg[8][2];
            #pragma unroll
            for (int nt=0;nt<8;nt++){
                int j0 = jb + nt*8 + 2*t4;
                breg[nt][0] = *(const uint32_t*)&g_biasH[h*NP + (rb+g  )*L + j0];
                breg[nt][1] = *(const uint32_t*)&g_biasH[h*NP + (rb+g+8)*L + j0];
            }
            float sacc[8][4];
            #pragma unroll
            for (int nt=0;nt<8;nt++)
                #pragma unroll
                for (int u=0;u<4;u++) sacc[nt][u]=0.f;
            #pragma unroll
            for (int kc=0;kc<2;kc++){
                #pragma unroll
                for (int pr=0;pr<4;pr++){
                    uint32_t b[4];
                    ldsm4(b, sK + ((jb + pr*16 + (lane&7) + ((lane>>4)<<3))*AS
                                    + kc*16 + (((lane>>3)&1)<<3))*2);
                    mma16(sacc[2*pr],   qa[kc], &b[0]);
                    mma16(sacc[2*pr+1], qa[kc], &b[2]);
                }
            }
            uint32_t ph[8][2];
            #pragma unroll
            for (int nt=0;nt<8;nt++){
                #pragma unroll
                for (int rp=0;rp<2;rp++){
                    float2 bi = __half22float2(*(const __half2*)&breg[nt][rp]);
                    float p0 = ex2(sacc[nt][2*rp]   + bi.x);
                    float p1 = ex2(sacc[nt][2*rp+1] + bi.y);
                    ph[nt][rp] = h2u(__floats2half2_rn(p0, p1));
                }
            }
            #pragma unroll
            for (int kc2=0;kc2<4;kc2++){
                uint32_t pa[4] = { ph[2*kc2][0], ph[2*kc2][1], ph[2*kc2+1][0], ph[2*kc2+1][1] };
                #pragma unroll
                for (int pr=0;pr<2;pr++){
                    uint32_t b[4];
                    ldsm4t(b, sV + ((jb + kc2*16 + (lane&7) + (((lane>>3)&1)<<3))*AS
                                     + pr*16 + ((lane>>4)<<3))*2);
                    mma16(oacc[2*pr],   pa, &b[0]);
                    mma16(oacc[2*pr+1], pa, &b[2]);
                }
                uint32_t bS[2];
                ldsm2t(bS, sV + ((jb + kc2*16 + (lane&7) + (((lane>>3)&1)<<3))*AS + 32)*2);
                mma16(oaccS, pa, bS);
            }
        }
        // row sums live in ones-column (local col 0 -> t4==0 lanes)
        float s0 = __shfl_sync(0xffffffffu, oaccS[0], lane & ~3);
        float s1 = __shfl_sync(0xffffffffu, oaccS[2], lane & ~3);
        float rinv[2] = { 1.f/s0, 1.f/s1 };
        #pragma unroll
        for (int nt=0;nt<4;nt++)
            #pragma unroll
            for (int rp=0;rp<2;rp++){
                int i = rb + g + 8*rp;
                int d = nt*8 + 2*t4;
                float2 gf = __half22float2(*(__half2*)&Gt[i*AS + d]);
                *(__half2*)&g_att[(size_t)(r*L+i)*DM + h*DK + d] = __floats2half2_rn(
                    oacc[nt][2*rp]  *rinv[rp]*gf.x,
                    oacc[nt][2*rp+1]*rinv[rp]*gf.y);
            }
    }
}

// ---------------------------------------------------------------------------
// K3: out = g_att @ Wo + bo. 256 thr, 64 rows/block -> 2 CTAs/SM.
// ---------------------------------------------------------------------------
__global__ __launch_bounds__(256,2) void k_out(const float* __restrict__ bo,
                                               float* __restrict__ dout)
{
    extern __shared__ char smem[];
    __half* At = (__half*)smem;                  // 64 x WS
    __half* Ws = (__half*)(smem + 64*WS*2);      // 128 x WS
    uint32_t sAt = smem_u32(At), sW = smem_u32(Ws);
    int tid = threadIdx.x, w = tid>>5, lane = tid&31, g = lane>>2, t4 = lane&3;
    int wm = w>>2, wn = w&3;
    int p0 = blockIdx.x*64;

    for (int e = tid; e < 1024; e += 256){
        int row = e>>4, c = e&15;
        ((uint4*)At)[row*17 + c] = ((const uint4*)g_att)[(size_t)(p0+row)*16 + c];
    }
    for (int e = tid; e < 128*WS/8; e += 256)
        ((uint4*)Ws)[e] = ((const uint4*)(g_wT + 4*128*WS))[e];
    __syncthreads();

    int rb = wm*32;
    float acc[2][4][4];
    #pragma unroll
    for (int mt=0;mt<2;mt++)
        #pragma unroll
        for (int nt=0;nt<4;nt++)
            #pragma unroll
            for (int u=0;u<4;u++) acc[mt][nt][u]=0.f;
    #pragma unroll
    for (int kc=0; kc<8; kc++){
        int k0 = kc*16;
        uint32_t a[2][4];
        #pragma unroll
        for (int mt=0;mt<2;mt++)
            ldsm4(a[mt], sAt + ((rb + mt*16 + (lane&15))*WS + k0 + ((lane>>4)<<3))*2);
        uint32_t b[4][4];
        #pragma unroll
        for (int pr=0;pr<2;pr++)
            ldsm4t(b[2*pr], sW + ((k0 + (lane&7) + (((lane>>3)&1)<<3))*WS
                                   + wn*32 + pr*16 + ((lane>>4)<<3))*2);
        #pragma unroll
        for (int mt=0;mt<2;mt++)
            #pragma unroll
            for (int nt=0;nt<4;nt++)
                mma16(acc[mt][nt], a[mt], &b[nt&~1][(nt&1)*2]);
    }
    #pragma unroll
    for (int mt=0;mt<2;mt++)
        #pragma unroll
        for (int nt=0;nt<4;nt++){
            int col = wn*32 + nt*8 + 2*t4;
            #pragma unroll
            for (int rp=0;rp<2;rp++){
                int row = p0 + rb + mt*16 + g + 8*rp;
                float2 o2 = { acc[mt][nt][2*rp] + bo[col],
                              acc[mt][nt][2*rp+1] + bo[col+1] };
                *(float2*)&dout[(size_t)row*DM + col] = o2;
            }
        }
}

// ---------------------------------------------------------------------------
extern "C" void kernel_launch(void* const* d_in, const int* in_sizes, int n_in,
                              void* d_out, int out_size)
{
    const float* z    = (const float*)d_in[0];
    const float* mask = (const float*)d_in[1];
    const float* ln_w = (const float*)d_in[2];
    const float* ln_b = (const float*)d_in[3];
    const float* Wq   = (const float*)d_in[4];
    const float* Wk   = (const float*)d_in[5];
    const float* Wv   = (const float*)d_in[6];
    const float* Wb   = (const float*)d_in[7];
    const float* Wg   = (const float*)d_in[8];
    const float* bg   = (const float*)d_in[9];
    const float* Wo   = (const float*)d_in[10];
    const float* bo   = (const float*)d_in[11];
    float* out = (float*)d_out;

    const int MAIN_SMEM = 192512;
    const int OUT_SMEM  = 64*WS*2 + 128*WS*2;   // 52224
    cudaFuncSetAttribute(k_main, cudaFuncAttributeMaxDynamicSharedMemorySize, MAIN_SMEM);
    cudaFuncSetAttribute(k_out,  cudaFuncAttributeMaxDynamicSharedMemorySize, OUT_SMEM);

    k_ln  <<<5 + NP/64, 512>>>(z, ln_w, ln_b, Wb, mask, Wq, Wk, Wv, Wg, Wo);
    k_main<<<dim3(L,NH), 512, MAIN_SMEM>>>(bg);
    k_out <<<NP/64, 256, OUT_SMEM>>>(bo, out);
}